// round 11
// baseline (speedup 1.0000x reference)
#include <cuda_runtime.h>
#include <cuda_bf16.h>
#include <cstddef>

// ---------------------------------------------------------------------------
// Problem constants
// ---------------------------------------------------------------------------
#define BATCH 32
#define SEQT  512
#define DMOD  512
#define HID   256
#define G4    1024          // 4*HID
#define ENT   64
#define REL   64
#define NLAY  2
#define MBT   (BATCH*SEQT)          // 16384 token rows
#define MPAIR (BATCH*ENT*ENT)       // 131072 pair rows
#define MENT  (BATCH*ENT)           // 2048 entity rows

// ---------------------------------------------------------------------------
// Device scratch (static allocation only — no cudaMalloc allowed)
// ---------------------------------------------------------------------------
__device__ __nv_bfloat16  g_xb[(size_t)MBT * DMOD];        // bf16 activations
__device__ __nv_bfloat16  g_xwb[(size_t)2 * MBT * G4];     // per-dir input proj (bf16)
__device__ float          g_bias[NLAY * 2 * G4];           // bih+bhh
__device__ int            g_sents[MBT];
__device__ int            g_ent[MENT * 3];
__device__ float          g_cont[(size_t)MENT * DMOD];
__device__ float          g_mask[MENT];
__device__ float          g_cw[(size_t)MENT * DMOD];
__device__ __nv_bfloat16  g_cwb[(size_t)MENT * DMOD];
__device__ float          g_rel1[(size_t)MENT * DMOD];
__device__ float          g_rel2[(size_t)MENT * DMOD];
__device__ __nv_bfloat16  g_Tb[(size_t)MPAIR * DMOD];      // pair hidden, bf16
// bf16 weight copies
__device__ __nv_bfloat16  g_wihb[(size_t)NLAY * 2 * G4 * DMOD];
__device__ __nv_bfloat16  g_r1b[DMOD * DMOD];
__device__ __nv_bfloat16  g_r2b[DMOD * DMOD];
__device__ __nv_bfloat16  g_pjb[DMOD * DMOD];
__device__ __nv_bfloat16  g_dcb[REL * DMOD];

__device__ __forceinline__ float tanh_a(float x) {
    float r;
    asm("tanh.approx.f32 %0, %1;" : "=f"(r) : "f"(x));
    return r;
}
__device__ __forceinline__ float sigm_a(float x) {
    return fmaf(tanh_a(0.5f * x), 0.5f, 0.5f);
}

// ---------------------------------------------------------------------------
// K0: canonicalize sents / ent_inds (int64-or-int32 auto-detect) -> int32
// ---------------------------------------------------------------------------
__global__ void prep_idx_kernel(const unsigned* __restrict__ sents_raw,
                                const unsigned* __restrict__ ent_raw) {
    __shared__ int s64f, e64f;
    int tid = threadIdx.x;
    if (tid == 0) {
        bool s64 = true;
        for (int i = 0; i < 64; i++)
            if (sents_raw[2 * i + 1] != 0u) { s64 = false; break; }
        bool e64 = true;
        for (int i = 0; i < 64; i++) {
            unsigned lo = ent_raw[2 * i], hi = ent_raw[2 * i + 1];
            unsigned expct = ((int)lo < 0) ? 0xFFFFFFFFu : 0u;
            if (hi != expct) { e64 = false; break; }
        }
        s64f = s64; e64f = e64;
    }
    __syncthreads();
    int s64 = s64f, e64 = e64f;
    for (int i = tid; i < MBT; i += blockDim.x)
        g_sents[i] = s64 ? (int)sents_raw[2 * i] : (int)sents_raw[i];
    for (int i = tid; i < MENT * 3; i += blockDim.x)
        g_ent[i] = e64 ? (int)ent_raw[2 * i] : (int)ent_raw[i];
}

__global__ void prep_bias_kernel(const float* __restrict__ bih,
                                 const float* __restrict__ bhh) {
    int i = blockIdx.x * blockDim.x + threadIdx.x;
    if (i < NLAY * 2 * G4) g_bias[i] = bih[i] + bhh[i];
}

// ---------------------------------------------------------------------------
// f32 -> bf16 vectorized convert (n4 float4-groups)
// ---------------------------------------------------------------------------
__global__ void f2b_kernel(const float* __restrict__ src,
                           __nv_bfloat16* __restrict__ dst, int n4) {
    int i = blockIdx.x * blockDim.x + threadIdx.x;
    if (i >= n4) return;
    float4 v = reinterpret_cast<const float4*>(src)[i];
    __nv_bfloat162 lo = __float22bfloat162_rn(make_float2(v.x, v.y));
    __nv_bfloat162 hi = __float22bfloat162_rn(make_float2(v.z, v.w));
    uint2 u;
    u.x = *reinterpret_cast<unsigned*>(&lo);
    u.y = *reinterpret_cast<unsigned*>(&hi);
    reinterpret_cast<uint2*>(dst)[i] = u;
}

// ---------------------------------------------------------------------------
// K2: embedding gather -> bf16 activations
// ---------------------------------------------------------------------------
__global__ void embed_kernel(const float* __restrict__ emb) {
    int row = blockIdx.x;
    int d = threadIdx.x;                               // 128 float4 lanes
    int tok = g_sents[row];
    float4 v = reinterpret_cast<const float4*>(emb + (size_t)tok * DMOD)[d];
    __nv_bfloat162 lo = __float22bfloat162_rn(make_float2(v.x, v.y));
    __nv_bfloat162 hi = __float22bfloat162_rn(make_float2(v.z, v.w));
    uint2 u;
    u.x = *reinterpret_cast<unsigned*>(&lo);
    u.y = *reinterpret_cast<unsigned*>(&hi);
    reinterpret_cast<uint2*>(g_xb + (size_t)row * DMOD)[d] = u;
}

// ---------------------------------------------------------------------------
// bf16 tensor-core GEMM: C[M,N] = A[M,K] @ W[N,K]^T + bias, fp32 accum.
// BM=128 BN=64 BK=32, 256 thr (8 warps, 4x2), warp tile 32x32 via mma.m16n8k16.
// GEN: A generated on the fly as relu(r1[b,j]+r2[b,i]); OUTB: bf16 output.
// gridDim.z batches independent (B, bias, C) strided problems in one launch.
// ---------------------------------------------------------------------------
template <bool GEN, bool OUTB, bool RELU>
__global__ __launch_bounds__(256)
void hgemm_nt(const __nv_bfloat16* __restrict__ A,
              const __nv_bfloat16* __restrict__ Bw,
              const float* __restrict__ bias,
              float* __restrict__ Cf, __nv_bfloat16* __restrict__ Cb,
              int M, int N, int K,
              const float* __restrict__ r1, const float* __restrict__ r2,
              size_t bzb, size_t bzbias, size_t bzc) {
    Bw   += (size_t)blockIdx.z * bzb;
    bias += (size_t)blockIdx.z * bzbias;
    if (OUTB) { if (Cb) Cb += (size_t)blockIdx.z * bzc; }
    else      { if (Cf) Cf += (size_t)blockIdx.z * bzc; }

    const int BM = 128, BN = 64, BK = 32, LDA = BK + 8;
    __shared__ __align__(16) __nv_bfloat16 As[BM * LDA];
    __shared__ __align__(16) __nv_bfloat16 Bs[BN * LDA];
    int tid = threadIdx.x;
    int row0 = blockIdx.y * BM, col0 = blockIdx.x * BN;

    int ar[2], ac[2];
    #pragma unroll
    for (int q = 0; q < 2; q++) {
        int idx = tid + q * 256;
        ar[q] = idx >> 2;
        ac[q] = (idx & 3) * 8;
    }
    int br = tid >> 2, bc = (tid & 3) * 8;

    float acc[2][4][4];
    #pragma unroll
    for (int i = 0; i < 2; i++)
        #pragma unroll
        for (int j = 0; j < 4; j++)
            #pragma unroll
            for (int c = 0; c < 4; c++) acc[i][j][c] = 0.f;

    uint4 ua[2], ub;
    auto fetch = [&](int kt) {
        #pragma unroll
        for (int q = 0; q < 2; q++) {
            int m = row0 + ar[q];
            if (!GEN) {
                ua[q] = *reinterpret_cast<const uint4*>(A + (size_t)m * K + kt + ac[q]);
            } else {
                int bb = m >> 12, ii = (m >> 6) & 63, jj = m & 63;
                const float4* p1 = reinterpret_cast<const float4*>(
                    r1 + ((size_t)(bb * ENT + jj)) * DMOD + kt + ac[q]);
                const float4* p2 = reinterpret_cast<const float4*>(
                    r2 + ((size_t)(bb * ENT + ii)) * DMOD + kt + ac[q]);
                float4 x0 = p1[0], x1 = p1[1], y0 = p2[0], y1 = p2[1];
                float f0 = fmaxf(x0.x + y0.x, 0.f), f1 = fmaxf(x0.y + y0.y, 0.f);
                float f2 = fmaxf(x0.z + y0.z, 0.f), f3 = fmaxf(x0.w + y0.w, 0.f);
                float f4 = fmaxf(x1.x + y1.x, 0.f), f5 = fmaxf(x1.y + y1.y, 0.f);
                float f6 = fmaxf(x1.z + y1.z, 0.f), f7 = fmaxf(x1.w + y1.w, 0.f);
                __nv_bfloat162 h0 = __float22bfloat162_rn(make_float2(f0, f1));
                __nv_bfloat162 h1 = __float22bfloat162_rn(make_float2(f2, f3));
                __nv_bfloat162 h2 = __float22bfloat162_rn(make_float2(f4, f5));
                __nv_bfloat162 h3 = __float22bfloat162_rn(make_float2(f6, f7));
                ua[q].x = *reinterpret_cast<unsigned*>(&h0);
                ua[q].y = *reinterpret_cast<unsigned*>(&h1);
                ua[q].z = *reinterpret_cast<unsigned*>(&h2);
                ua[q].w = *reinterpret_cast<unsigned*>(&h3);
            }
        }
        ub = *reinterpret_cast<const uint4*>(Bw + (size_t)(col0 + br) * K + kt + bc);
    };

    fetch(0);
    int w = tid >> 5, wm = w & 3, wn = w >> 2, l = tid & 31;
    int lr = l >> 2, lc = (l & 3) * 2;

    for (int kt = 0; kt < K; kt += BK) {
        __syncthreads();
        *reinterpret_cast<uint4*>(&As[ar[0] * LDA + ac[0]]) = ua[0];
        *reinterpret_cast<uint4*>(&As[ar[1] * LDA + ac[1]]) = ua[1];
        *reinterpret_cast<uint4*>(&Bs[br * LDA + bc]) = ub;
        __syncthreads();
        if (kt + BK < K) fetch(kt + BK);

        #pragma unroll
        for (int s = 0; s < 2; s++) {
            int k0 = s * 16;
            unsigned a[2][4], b[4][2];
            #pragma unroll
            for (int i = 0; i < 2; i++) {
                const __nv_bfloat16* p = &As[(wm * 32 + i * 16 + lr) * LDA + k0 + lc];
                a[i][0] = *reinterpret_cast<const unsigned*>(p);
                a[i][1] = *reinterpret_cast<const unsigned*>(p + 8 * LDA);
                a[i][2] = *reinterpret_cast<const unsigned*>(p + 8);
                a[i][3] = *reinterpret_cast<const unsigned*>(p + 8 * LDA + 8);
            }
            #pragma unroll
            for (int j = 0; j < 4; j++) {
                const __nv_bfloat16* p = &Bs[(wn * 32 + j * 8 + lr) * LDA + k0 + lc];
                b[j][0] = *reinterpret_cast<const unsigned*>(p);
                b[j][1] = *reinterpret_cast<const unsigned*>(p + 8);
            }
            #pragma unroll
            for (int i = 0; i < 2; i++)
                #pragma unroll
                for (int j = 0; j < 4; j++)
                    asm volatile(
                        "mma.sync.aligned.m16n8k16.row.col.f32.bf16.bf16.f32 "
                        "{%0,%1,%2,%3},{%4,%5,%6,%7},{%8,%9},{%0,%1,%2,%3};"
                        : "+f"(acc[i][j][0]), "+f"(acc[i][j][1]),
                          "+f"(acc[i][j][2]), "+f"(acc[i][j][3])
                        : "r"(a[i][0]), "r"(a[i][1]), "r"(a[i][2]), "r"(a[i][3]),
                          "r"(b[j][0]), "r"(b[j][1]));
        }
    }

    // epilogue
    #pragma unroll
    for (int i = 0; i < 2; i++) {
        int m = row0 + wm * 32 + i * 16 + lr;
        #pragma unroll
        for (int j = 0; j < 4; j++) {
            int col = col0 + wn * 32 + j * 8 + lc;
            float b0 = bias[col], b1 = bias[col + 1];
            float v0 = acc[i][j][0] + b0, v1 = acc[i][j][1] + b1;
            float v2 = acc[i][j][2] + b0, v3 = acc[i][j][3] + b1;
            if (RELU) {
                v0 = fmaxf(v0, 0.f); v1 = fmaxf(v1, 0.f);
                v2 = fmaxf(v2, 0.f); v3 = fmaxf(v3, 0.f);
            }
            if (OUTB) {
                __nv_bfloat162 p0 = __float22bfloat162_rn(make_float2(v0, v1));
                __nv_bfloat162 p1 = __float22bfloat162_rn(make_float2(v2, v3));
                *reinterpret_cast<__nv_bfloat162*>(Cb + (size_t)m * N + col) = p0;
                *reinterpret_cast<__nv_bfloat162*>(Cb + (size_t)(m + 8) * N + col) = p1;
            } else {
                *reinterpret_cast<float2*>(Cf + (size_t)m * N + col) = make_float2(v0, v1);
                *reinterpret_cast<float2*>(Cf + (size_t)(m + 8) * N + col) = make_float2(v2, v3);
            }
        }
    }
}

// ---------------------------------------------------------------------------
// K3: LSTM recurrence on tensor cores, 4-CTA cluster, 2 batches per cluster.
// Same structure as the R8/R10 winner, but the per-step cluster.sync is
// replaced with an mbarrier handshake: each CTA hosts one mbarrier
// (count = 128 = 32 storing threads x 4 ranks). Each storing thread does its
// 2 remote st.shared::cluster then mbarrier.arrive.release.cluster on all 4
// ranks; all threads wait with try_wait.parity.acquire.cluster. Phase p is
// completed by step p-1's arrivals (phase 0 primed after init). Skew safety:
// overwriting buffer[par] at step s+2 requires passing wait(s+2), which needs
// every rank's step-(s+1) arrival, which follows that rank's read of
// buffer[par]. x-projection is bf16; only the bf16 y mirror is written.
// ---------------------------------------------------------------------------
__global__ void __cluster_dims__(4, 1, 1) __launch_bounds__(256, 1)
lstm_mma_kernel(const __nv_bfloat16* __restrict__ xw,
                const float* __restrict__ whh_l,   // fp32 [2][G4][HID]
                __nv_bfloat16* __restrict__ yb) {
    __shared__ __align__(16) __nv_bfloat16 hA[2][2][264];  // [par][batch][k]
    __shared__ __align__(16) float zs[2][260];             // [batch][n]
    __shared__ __align__(8) unsigned long long s_mbar;

    int tid = threadIdx.x;
    int w = tid >> 5, l = tid & 31;
    int gq = l >> 2, t2 = (l & 3) * 2;
    int rank = blockIdx.x & 3;
    int cid  = blockIdx.x >> 2;
    int dir  = cid >> 4;
    int bp   = cid & 15;
    int j0   = rank * 64;

    unsigned mb_local;
    asm("{ .reg .u64 t; cvta.to.shared.u64 t, %1; cvt.u32.u64 %0, t; }"
        : "=r"(mb_local) : "l"(&s_mbar));
    if (tid == 0)
        asm volatile("mbarrier.init.shared.b64 [%0], %1;"
                     :: "r"(mb_local), "r"(128u) : "memory");

    // zero h staging (both parities)
    for (int i = tid; i < 2 * 2 * 264; i += 256)
        (&hA[0][0][0])[i] = __float2bfloat16(0.f);

    // ---- B-fragment preload: W[n][k] resident in registers ----------------
    unsigned Bf[4][16][2];
    {
        const float* wd = whh_l + (size_t)dir * G4 * HID;
        #pragma unroll
        for (int nt = 0; nt < 4; nt++) {
            int n = w * 32 + nt * 8 + gq;            // CTA-local gate index
            int g = n >> 6, jl = n & 63;
            const float* wp = wd + (size_t)(g * 256 + j0 + jl) * HID;
            #pragma unroll
            for (int kt = 0; kt < 16; kt++) {
                int k0 = kt * 16 + t2;
                float2 wa = *reinterpret_cast<const float2*>(wp + k0);
                float2 wb = *reinterpret_cast<const float2*>(wp + k0 + 8);
                __nv_bfloat162 qa = __float22bfloat162_rn(wa);
                __nv_bfloat162 qb = __float22bfloat162_rn(wb);
                Bf[nt][kt][0] = *reinterpret_cast<unsigned*>(&qa);
                Bf[nt][kt][1] = *reinterpret_cast<unsigned*>(&qb);
            }
        }
    }
    __syncthreads();
    asm volatile("barrier.cluster.arrive.aligned;" ::: "memory");
    asm volatile("barrier.cluster.wait.aligned;" ::: "memory");

    // priming: complete phase 0 (h0 buffers pre-zeroed)
    if (tid < 64 && !(tid & 1)) {
        #pragma unroll
        for (int r = 0; r < 4; r++)
            asm volatile(
                "{ .reg .b32 ra; mapa.shared::cluster.u32 ra, %0, %1;\n\t"
                "mbarrier.arrive.release.cluster.shared::cluster.b64 _, [ra]; }"
                :: "r"(mb_local), "r"(r) : "memory");
    }

    int bg0 = bp * 2;
    const __nv_bfloat16* xd = xw + (size_t)dir * MBT * G4;
    int xcol = (w >> 1) * 256 + j0 + (w & 1) * 32;   // global z-col base
    int brow = gq & 1;                               // A-row (= batch) for lanes 0-7

    // owner mapping: tid<64 -> j = tid (both batches)
    int jg = j0 + tid;
    size_t y0off = (size_t)bg0 * SEQT * DMOD + dir * HID + jg;
    size_t y1off = y0off + (size_t)SEQT * DMOD;
    float c0 = 0.f, c1 = 0.f;

    unsigned hAbase;
    asm("{ .reg .u64 t; cvta.to.shared.u64 t, %1; cvt.u32.u64 %0, t; }"
        : "=r"(hAbase) : "l"(&hA[0][0][0]));

    // first step's x (accumulator init values, lanes 0-7)
    float2 xi[4];
    {
        int t0 = dir ? SEQT - 1 : 0;
        #pragma unroll
        for (int nt = 0; nt < 4; nt++) {
            xi[nt] = make_float2(0.f, 0.f);
            if (l < 8) {
                __nv_bfloat162 u = *reinterpret_cast<const __nv_bfloat162*>(
                    xd + ((size_t)(bg0 + brow) * SEQT + t0) * G4 + xcol + nt * 8 + t2);
                xi[nt] = __bfloat1622float2(u);
            }
        }
    }

    unsigned zc = 0u;
    int par = 0;
    for (int s = 0; s < SEQT; s++) {
        int t = dir ? (SEQT - 1 - s) : s;

        // wait for hA[par] to be filled (phase s; parity s&1)
        {
            unsigned parity = (unsigned)(s & 1);
            asm volatile(
                "{ .reg .pred p;\n\t"
                "WAITL%=:\n\t"
                "mbarrier.try_wait.parity.acquire.cluster.shared::cta.b64 p, [%0], %1, 0x989680;\n\t"
                "@!p bra WAITL%=;\n\t}"
                :: "r"(mb_local), "r"(parity) : "memory");
        }

        // prefetch next step's x
        int sn = (s + 1 < SEQT) ? s + 1 : s;
        int tn = dir ? (SEQT - 1 - sn) : sn;
        float2 xn[4];
        #pragma unroll
        for (int nt = 0; nt < 4; nt++) {
            xn[nt] = make_float2(0.f, 0.f);
            if (l < 8) {
                __nv_bfloat162 u = *reinterpret_cast<const __nv_bfloat162*>(
                    xd + ((size_t)(bg0 + brow) * SEQT + tn) * G4 + xcol + nt * 8 + t2);
                xn[nt] = __bfloat1622float2(u);
            }
        }

        // accumulators = x (bias folded); rows 8,9 unused -> 0
        float acc[4][4];
        #pragma unroll
        for (int nt = 0; nt < 4; nt++) {
            acc[nt][0] = xi[nt].x; acc[nt][1] = xi[nt].y;
            acc[nt][2] = 0.f;      acc[nt][3] = 0.f;
        }

        // mma over k = 256 (16 tiles)
        const __nv_bfloat16* hrow = &hA[par][brow][0];
        #pragma unroll
        for (int kt = 0; kt < 16; kt++) {
            unsigned a0 = 0u, a2 = 0u;
            if (l < 8) {
                a0 = *reinterpret_cast<const unsigned*>(hrow + kt * 16 + t2);
                a2 = *reinterpret_cast<const unsigned*>(hrow + kt * 16 + t2 + 8);
            }
            #pragma unroll
            for (int nt = 0; nt < 4; nt++)
                asm volatile(
                    "mma.sync.aligned.m16n8k16.row.col.f32.bf16.bf16.f32 "
                    "{%0,%1,%2,%3},{%4,%5,%6,%7},{%8,%9},{%0,%1,%2,%3};"
                    : "+f"(acc[nt][0]), "+f"(acc[nt][1]),
                      "+f"(acc[nt][2]), "+f"(acc[nt][3])
                    : "r"(a0), "r"(zc), "r"(a2), "r"(zc),
                      "r"(Bf[nt][kt][0]), "r"(Bf[nt][kt][1]));
        }

        // z -> smem (lanes 0-7 hold rows 0,1)
        if (l < 8) {
            #pragma unroll
            for (int nt = 0; nt < 4; nt++)
                *reinterpret_cast<float2*>(&zs[brow][w * 32 + nt * 8 + t2]) =
                    make_float2(acc[nt][0], acc[nt][1]);
        }
        __syncthreads();

        // owners: MUFU activations + bf16 y + DSMEM broadcast + remote arrive
        if (tid < 64) {
            float z0[4], z1[4];
            #pragma unroll
            for (int g = 0; g < 4; g++) {
                z0[g] = zs[0][g * 64 + tid];
                z1[g] = zs[1][g * 64 + tid];
            }
            c0 = sigm_a(z0[1]) * c0 + sigm_a(z0[0]) * tanh_a(z0[2]);
            float h0 = sigm_a(z0[3]) * tanh_a(c0);
            c1 = sigm_a(z1[1]) * c1 + sigm_a(z1[0]) * tanh_a(z1[2]);
            float h1 = sigm_a(z1[3]) * tanh_a(c1);
            __nv_bfloat16 hb0 = __float2bfloat16(h0);
            __nv_bfloat16 hb1 = __float2bfloat16(h1);
            yb[y0off + (size_t)t * DMOD] = hb0;
            yb[y1off + (size_t)t * DMOD] = hb1;

            unsigned u0 = (unsigned)__bfloat16_as_ushort(hb0);
            unsigned u1 = (unsigned)__bfloat16_as_ushort(hb1);
            unsigned n0 = __shfl_down_sync(0xffffffffu, u0, 1);
            unsigned n1 = __shfl_down_sync(0xffffffffu, u1, 1);
            if (!(tid & 1)) {
                unsigned pk0 = u0 | (n0 << 16);
                unsigned pk1 = u1 | (n1 << 16);
                unsigned d0 = hAbase + (unsigned)((((par ^ 1) * 2 + 0) * 264 + jg) * 2);
                unsigned d1 = d0 + 264u * 2u;
                #pragma unroll
                for (int r = 0; r < 4; r++) {
                    asm volatile(
                        "{ .reg .b32 ra; mapa.shared::cluster.u32 ra, %0, %1; "
                        "st.shared::cluster.b32 [ra], %2; }"
                        :: "r"(d0), "r"(r), "r"(pk0) : "memory");
                    asm volatile(
                        "{ .reg .b32 ra; mapa.shared::cluster.u32 ra, %0, %1; "
                        "st.shared::cluster.b32 [ra], %2; }"
                        :: "r"(d1), "r"(r), "r"(pk1) : "memory");
                }
                #pragma unroll
                for (int r = 0; r < 4; r++)
                    asm volatile(
                        "{ .reg .b32 ra; mapa.shared::cluster.u32 ra, %0, %1;\n\t"
                        "mbarrier.arrive.release.cluster.shared::cluster.b64 _, [ra]; }"
                        :: "r"(mb_local), "r"(r) : "memory");
            }
        }

        par ^= 1;
        #pragma unroll
        for (int nt = 0; nt < 4; nt++) xi[nt] = xn[nt];
    }

    // keep cluster alive until all in-flight remote ops complete
    asm volatile("barrier.cluster.arrive.aligned;" ::: "memory");
    asm volatile("barrier.cluster.wait.aligned;" ::: "memory");
}

// ---------------------------------------------------------------------------
// K4: zero cont + mask
// ---------------------------------------------------------------------------
__global__ void zero_kernel() {
    int idx = blockIdx.x * blockDim.x + threadIdx.x;
    const int NC4 = (MENT * DMOD) / 4;
    if (idx < NC4) reinterpret_cast<float4*>(g_cont)[idx] = make_float4(0, 0, 0, 0);
    if (idx < MENT / 4) reinterpret_cast<float4*>(g_mask)[idx] = make_float4(0, 0, 0, 0);
}

// ---------------------------------------------------------------------------
// K5: ragged span mean-pool + scatter-add (atomic); reads bf16 activations
// ---------------------------------------------------------------------------
__global__ void span_pool_kernel(const __nv_bfloat16* __restrict__ x) {
    int be = blockIdx.x;
    int b = be >> 6;
    const int* ei = g_ent + be * 3;
    int id = ei[0], st = ei[1], en = ei[2];
    if (id < 0 || id >= ENT) return;
    int lo = st, hi = en;
    float sgn = 1.f;
    if (en < st) { lo = en; hi = st; sgn = -1.f; }
    lo = max(lo, 0); hi = min(hi, SEQT);
    float len = (float)max(en - st, 1);

    int d = threadIdx.x;                 // 128 lanes, 4 bf16 each
    float4 acc = make_float4(0, 0, 0, 0);
    const uint2* xp =
        reinterpret_cast<const uint2*>(x + (size_t)b * SEQT * DMOD) + d;
    for (int t = lo; t < hi; t++) {
        uint2 u = xp[(size_t)t * (DMOD / 4)];
        float2 a = __bfloat1622float2(*reinterpret_cast<__nv_bfloat162*>(&u.x));
        float2 bb = __bfloat1622float2(*reinterpret_cast<__nv_bfloat162*>(&u.y));
        acc.x += a.x; acc.y += a.y; acc.z += bb.x; acc.w += bb.y;
    }
    float invl = sgn / len;
    float* cp = g_cont + ((size_t)(b * ENT + id)) * DMOD + d * 4;
    atomicAdd(cp + 0, acc.x * invl);
    atomicAdd(cp + 1, acc.y * invl);
    atomicAdd(cp + 2, acc.z * invl);
    atomicAdd(cp + 3, acc.w * invl);
    if (d == 0) atomicAdd(&g_mask[b * ENT + id], 1.f);
}

// ---------------------------------------------------------------------------
// K6: LayerNorm over D=512 -> fp32 cw
// ---------------------------------------------------------------------------
__global__ __launch_bounds__(256)
void ln_kernel(const float* __restrict__ gw, const float* __restrict__ gb) {
    int row = blockIdx.x;
    int tid = threadIdx.x;
    const float* xr = g_cont + (size_t)row * DMOD;
    float v0 = xr[tid], v1 = xr[tid + 256];

    __shared__ float red[8];
    __shared__ float bc;
    int lane = tid & 31, warp = tid >> 5;

    float s = v0 + v1;
    #pragma unroll
    for (int o = 16; o; o >>= 1) s += __shfl_xor_sync(0xffffffffu, s, o);
    if (lane == 0) red[warp] = s;
    __syncthreads();
    if (tid == 0) {
        float t = 0;
        #pragma unroll
        for (int w = 0; w < 8; w++) t += red[w];
        bc = t * (1.f / DMOD);
    }
    __syncthreads();
    float mu = bc;
    __syncthreads();

    float d0 = v0 - mu, d1 = v1 - mu;
    float q = d0 * d0 + d1 * d1;
    #pragma unroll
    for (int o = 16; o; o >>= 1) q += __shfl_xor_sync(0xffffffffu, q, o);
    if (lane == 0) red[warp] = q;
    __syncthreads();
    if (tid == 0) {
        float t = 0;
        #pragma unroll
        for (int w = 0; w < 8; w++) t += red[w];
        bc = t * (1.f / DMOD);
    }
    __syncthreads();
    float inv = rsqrtf(bc + 1e-5f);

    float* o = g_cw + (size_t)row * DMOD;
    o[tid]       = d0 * inv * gw[tid]       + gb[tid];
    o[tid + 256] = d1 * inv * gw[tid + 256] + gb[tid + 256];
}

// ---------------------------------------------------------------------------
// K7: mask + log_softmax over R=64 (one warp per row, in-place on d_out)
// ---------------------------------------------------------------------------
__global__ __launch_bounds__(256)
void lsm_kernel(float* __restrict__ out) {
    int warp = threadIdx.x >> 5, lane = threadIdx.x & 31;
    int row = blockIdx.x * 8 + warp;
    int b = row >> 12, i = (row >> 6) & 63, j = row & 63;
    float m = fminf(g_mask[b * ENT + i], 1.f) * fminf(g_mask[b * ENT + j], 1.f);
    float* p = out + (size_t)row * REL;
    float v0 = p[lane] * m, v1 = p[lane + 32] * m;
    float mx = fmaxf(v0, v1);
    #pragma unroll
    for (int o = 16; o; o >>= 1) mx = fmaxf(mx, __shfl_xor_sync(0xffffffffu, mx, o));
    float s = expf(v0 - mx) + expf(v1 - mx);
    #pragma unroll
    for (int o = 16; o; o >>= 1) s += __shfl_xor_sync(0xffffffffu, s, o);
    float lse = mx + logf(s);
    p[lane] = v0 - lse;
    p[lane + 32] = v1 - lse;
}

// ---------------------------------------------------------------------------
// Host launch
// ---------------------------------------------------------------------------
extern "C" void kernel_launch(void* const* d_in, const int* in_sizes, int n_in,
                              void* d_out, int out_size) {
    int off = (in_sizes[2] == 1) ? 0 : -1;
    const unsigned* sents_raw = (const unsigned*)d_in[0];
    const unsigned* ent_raw   = (const unsigned*)d_in[1];
    const float* emb    = (const float*)d_in[3 + off];
    const float* Wih    = (const float*)d_in[4 + off];
    const float* Whh    = (const float*)d_in[5 + off];
    const float* bih    = (const float*)d_in[6 + off];
    const float* bhh    = (const float*)d_in[7 + off];
    const float* ln_g   = (const float*)d_in[8 + off];
    const float* ln_b   = (const float*)d_in[9 + off];
    const float* rel1_w = (const float*)d_in[10 + off];
    const float* rel1_b = (const float*)d_in[11 + off];
    const float* rel2_w = (const float*)d_in[12 + off];
    const float* rel2_b = (const float*)d_in[13 + off];
    const float* proj_w = (const float*)d_in[14 + off];
    const float* proj_b = (const float*)d_in[15 + off];
    const float* dec_w  = (const float*)d_in[16 + off];
    const float* dec_b  = (const float*)d_in[17 + off];
    float* out = (float*)d_out;

    float *p_bias, *p_cw, *p_r1, *p_r2;
    __nv_bfloat16 *p_xb, *p_xwb, *p_cwb, *p_Tb, *p_wihb, *p_r1b, *p_r2b, *p_pjb, *p_dcb;
    cudaGetSymbolAddress((void**)&p_bias, g_bias);
    cudaGetSymbolAddress((void**)&p_cw, g_cw);
    cudaGetSymbolAddress((void**)&p_r1, g_rel1);
    cudaGetSymbolAddress((void**)&p_r2, g_rel2);
    cudaGetSymbolAddress((void**)&p_xb, g_xb);
    cudaGetSymbolAddress((void**)&p_xwb, g_xwb);
    cudaGetSymbolAddress((void**)&p_cwb, g_cwb);
    cudaGetSymbolAddress((void**)&p_Tb, g_Tb);
    cudaGetSymbolAddress((void**)&p_wihb, g_wihb);
    cudaGetSymbolAddress((void**)&p_r1b, g_r1b);
    cudaGetSymbolAddress((void**)&p_r2b, g_r2b);
    cudaGetSymbolAddress((void**)&p_pjb, g_pjb);
    cudaGetSymbolAddress((void**)&p_dcb, g_dcb);

    prep_idx_kernel<<<1, 256>>>(sents_raw, ent_raw);
    prep_bias_kernel<<<16, 256>>>(bih, bhh);
    f2b_kernel<<<2048, 256>>>(Wih, p_wihb, NLAY * 2 * G4 * DMOD / 4);
    f2b_kernel<<<256, 256>>>(rel1_w, p_r1b, DMOD * DMOD / 4);
    f2b_kernel<<<256, 256>>>(rel2_w, p_r2b, DMOD * DMOD / 4);
    f2b_kernel<<<256, 256>>>(proj_w, p_pjb, DMOD * DMOD / 4);
    f2b_kernel<<<32, 256>>>(dec_w, p_dcb, REL * DMOD / 4);
    embed_kernel<<<MBT, 128>>>(emb);

    for (int l = 0; l < NLAY; l++) {
        // both directions in one launch (gridDim.z = 2), bf16 output
        hgemm_nt<false, true, false><<<dim3(G4 / 64, MBT / 128, 2), 256>>>(
            p_xb, p_wihb + (size_t)(l * 2) * G4 * DMOD,
            p_bias + (l * 2) * G4,
            nullptr, p_xwb,
            MBT, G4, DMOD, nullptr, nullptr,
            (size_t)G4 * DMOD, (size_t)G4, (size_t)MBT * G4);
        // writes bf16 y into g_xb (next layer's input / final pooling source)
        lstm_mma_kernel<<<128, 256>>>(
            p_xwb, Whh + (size_t)l * 2 * G4 * HID, p_xb);
    }

    zero_kernel<<<1024, 256>>>();
    span_pool_kernel<<<MENT, 128>>>(p_xb);
    ln_kernel<<<MENT, 256>>>(ln_g, ln_b);
    f2b_kernel<<<(MENT * DMOD / 4 + 255) / 256, 256>>>(p_cw, p_cwb, MENT * DMOD / 4);

    hgemm_nt<false, false, false><<<dim3(DMOD / 64, MENT / 128), 256>>>(
        p_cwb, p_r1b, rel1_b, p_r1, nullptr, MENT, DMOD, DMOD, nullptr, nullptr,
        0, 0, 0);
    hgemm_nt<false, false, false><<<dim3(DMOD / 64, MENT / 128), 256>>>(
        p_cwb, p_r2b, rel2_b, p_r2, nullptr, MENT, DMOD, DMOD, nullptr, nullptr,
        0, 0, 0);

    // pairwise: Tb = relu( relu(r1_j + r2_i) @ proj_w.T + proj_b )  (bf16 out)
    hgemm_nt<true, true, true><<<dim3(DMOD / 64, MPAIR / 128), 256>>>(
        nullptr, p_pjb, proj_b, nullptr, p_Tb, MPAIR, DMOD, DMOD, p_r1, p_r2,
        0, 0, 0);

    // logits = Tb @ dec_w.T + dec_b  -> d_out (fp32)
    hgemm_nt<false, false, false><<<dim3(REL / 64, MPAIR / 128), 256>>>(
        p_Tb, p_dcb, dec_b, out, nullptr, MPAIR, REL, DMOD, nullptr, nullptr,
        0, 0, 0);

    lsm_kernel<<<MPAIR / 8, 256>>>(out);
}

// round 12
// speedup vs baseline: 1.0526x; 1.0526x over previous
#include <cuda_runtime.h>
#include <cuda_bf16.h>
#include <cstddef>

// ---------------------------------------------------------------------------
// Problem constants
// ---------------------------------------------------------------------------
#define BATCH 32
#define SEQT  512
#define DMOD  512
#define HID   256
#define G4    1024          // 4*HID
#define ENT   64
#define REL   64
#define NLAY  2
#define MBT   (BATCH*SEQT)          // 16384 token rows
#define MPAIR (BATCH*ENT*ENT)       // 131072 pair rows
#define MENT  (BATCH*ENT)           // 2048 entity rows

// ---------------------------------------------------------------------------
// Device scratch (static allocation only — no cudaMalloc allowed)
// ---------------------------------------------------------------------------
__device__ __nv_bfloat16  g_xb[(size_t)MBT * DMOD];        // bf16 activations
__device__ __nv_bfloat16  g_xwb[(size_t)2 * MBT * G4];     // per-dir input proj (bf16)
__device__ float          g_bias[NLAY * 2 * G4];           // bih+bhh
__device__ int            g_sents[MBT];
__device__ int            g_ent[MENT * 3];
__device__ float          g_cont[(size_t)MENT * DMOD];
__device__ float          g_mask[MENT];
__device__ float          g_cw[(size_t)MENT * DMOD];
__device__ __nv_bfloat16  g_cwb[(size_t)MENT * DMOD];
__device__ float          g_rel1[(size_t)MENT * DMOD];
__device__ float          g_rel2[(size_t)MENT * DMOD];
__device__ __nv_bfloat16  g_Tb[(size_t)MPAIR * DMOD];      // pair hidden, bf16
// bf16 weight copies
__device__ __nv_bfloat16  g_wihb[(size_t)NLAY * 2 * G4 * DMOD];
__device__ __nv_bfloat16  g_r1b[DMOD * DMOD];
__device__ __nv_bfloat16  g_r2b[DMOD * DMOD];
__device__ __nv_bfloat16  g_pjb[DMOD * DMOD];
__device__ __nv_bfloat16  g_dcb[REL * DMOD];

__device__ __forceinline__ float tanh_a(float x) {
    float r;
    asm("tanh.approx.f32 %0, %1;" : "=f"(r) : "f"(x));
    return r;
}
__device__ __forceinline__ float sigm_a(float x) {
    return fmaf(tanh_a(0.5f * x), 0.5f, 0.5f);
}

// ---------------------------------------------------------------------------
// K0: canonicalize sents / ent_inds (int64-or-int32 auto-detect) -> int32
// ---------------------------------------------------------------------------
__global__ void prep_idx_kernel(const unsigned* __restrict__ sents_raw,
                                const unsigned* __restrict__ ent_raw) {
    __shared__ int s64f, e64f;
    int tid = threadIdx.x;
    if (tid == 0) {
        bool s64 = true;
        for (int i = 0; i < 64; i++)
            if (sents_raw[2 * i + 1] != 0u) { s64 = false; break; }
        bool e64 = true;
        for (int i = 0; i < 64; i++) {
            unsigned lo = ent_raw[2 * i], hi = ent_raw[2 * i + 1];
            unsigned expct = ((int)lo < 0) ? 0xFFFFFFFFu : 0u;
            if (hi != expct) { e64 = false; break; }
        }
        s64f = s64; e64f = e64;
    }
    __syncthreads();
    int s64 = s64f, e64 = e64f;
    for (int i = tid; i < MBT; i += blockDim.x)
        g_sents[i] = s64 ? (int)sents_raw[2 * i] : (int)sents_raw[i];
    for (int i = tid; i < MENT * 3; i += blockDim.x)
        g_ent[i] = e64 ? (int)ent_raw[2 * i] : (int)ent_raw[i];
}

__global__ void prep_bias_kernel(const float* __restrict__ bih,
                                 const float* __restrict__ bhh) {
    int i = blockIdx.x * blockDim.x + threadIdx.x;
    if (i < NLAY * 2 * G4) g_bias[i] = bih[i] + bhh[i];
}

// ---------------------------------------------------------------------------
// f32 -> bf16 vectorized convert (n4 float4-groups)
// ---------------------------------------------------------------------------
__global__ void f2b_kernel(const float* __restrict__ src,
                           __nv_bfloat16* __restrict__ dst, int n4) {
    int i = blockIdx.x * blockDim.x + threadIdx.x;
    if (i >= n4) return;
    float4 v = reinterpret_cast<const float4*>(src)[i];
    __nv_bfloat162 lo = __float22bfloat162_rn(make_float2(v.x, v.y));
    __nv_bfloat162 hi = __float22bfloat162_rn(make_float2(v.z, v.w));
    uint2 u;
    u.x = *reinterpret_cast<unsigned*>(&lo);
    u.y = *reinterpret_cast<unsigned*>(&hi);
    reinterpret_cast<uint2*>(dst)[i] = u;
}

// ---------------------------------------------------------------------------
// K2: embedding gather -> bf16 activations
// ---------------------------------------------------------------------------
__global__ void embed_kernel(const float* __restrict__ emb) {
    int row = blockIdx.x;
    int d = threadIdx.x;                               // 128 float4 lanes
    int tok = g_sents[row];
    float4 v = reinterpret_cast<const float4*>(emb + (size_t)tok * DMOD)[d];
    __nv_bfloat162 lo = __float22bfloat162_rn(make_float2(v.x, v.y));
    __nv_bfloat162 hi = __float22bfloat162_rn(make_float2(v.z, v.w));
    uint2 u;
    u.x = *reinterpret_cast<unsigned*>(&lo);
    u.y = *reinterpret_cast<unsigned*>(&hi);
    reinterpret_cast<uint2*>(g_xb + (size_t)row * DMOD)[d] = u;
}

// ---------------------------------------------------------------------------
// bf16 tensor-core GEMM: C[M,N] = A[M,K] @ W[N,K]^T + bias, fp32 accum.
// BM=128 BN=64 BK=32, 256 thr (8 warps, 4x2), warp tile 32x32 via mma.m16n8k16.
// GEN: A generated on the fly as relu(r1[b,j]+r2[b,i]); OUTB: bf16 output.
// gridDim.z batches independent (B, bias, C) strided problems in one launch.
// ---------------------------------------------------------------------------
template <bool GEN, bool OUTB, bool RELU>
__global__ __launch_bounds__(256)
void hgemm_nt(const __nv_bfloat16* __restrict__ A,
              const __nv_bfloat16* __restrict__ Bw,
              const float* __restrict__ bias,
              float* __restrict__ Cf, __nv_bfloat16* __restrict__ Cb,
              int M, int N, int K,
              const float* __restrict__ r1, const float* __restrict__ r2,
              size_t bzb, size_t bzbias, size_t bzc) {
    Bw   += (size_t)blockIdx.z * bzb;
    bias += (size_t)blockIdx.z * bzbias;
    if (OUTB) { if (Cb) Cb += (size_t)blockIdx.z * bzc; }
    else      { if (Cf) Cf += (size_t)blockIdx.z * bzc; }

    const int BM = 128, BN = 64, BK = 32, LDA = BK + 8;
    __shared__ __align__(16) __nv_bfloat16 As[BM * LDA];
    __shared__ __align__(16) __nv_bfloat16 Bs[BN * LDA];
    int tid = threadIdx.x;
    int row0 = blockIdx.y * BM, col0 = blockIdx.x * BN;

    int ar[2], ac[2];
    #pragma unroll
    for (int q = 0; q < 2; q++) {
        int idx = tid + q * 256;
        ar[q] = idx >> 2;
        ac[q] = (idx & 3) * 8;
    }
    int br = tid >> 2, bc = (tid & 3) * 8;

    float acc[2][4][4];
    #pragma unroll
    for (int i = 0; i < 2; i++)
        #pragma unroll
        for (int j = 0; j < 4; j++)
            #pragma unroll
            for (int c = 0; c < 4; c++) acc[i][j][c] = 0.f;

    uint4 ua[2], ub;
    auto fetch = [&](int kt) {
        #pragma unroll
        for (int q = 0; q < 2; q++) {
            int m = row0 + ar[q];
            if (!GEN) {
                ua[q] = *reinterpret_cast<const uint4*>(A + (size_t)m * K + kt + ac[q]);
            } else {
                int bb = m >> 12, ii = (m >> 6) & 63, jj = m & 63;
                const float4* p1 = reinterpret_cast<const float4*>(
                    r1 + ((size_t)(bb * ENT + jj)) * DMOD + kt + ac[q]);
                const float4* p2 = reinterpret_cast<const float4*>(
                    r2 + ((size_t)(bb * ENT + ii)) * DMOD + kt + ac[q]);
                float4 x0 = p1[0], x1 = p1[1], y0 = p2[0], y1 = p2[1];
                float f0 = fmaxf(x0.x + y0.x, 0.f), f1 = fmaxf(x0.y + y0.y, 0.f);
                float f2 = fmaxf(x0.z + y0.z, 0.f), f3 = fmaxf(x0.w + y0.w, 0.f);
                float f4 = fmaxf(x1.x + y1.x, 0.f), f5 = fmaxf(x1.y + y1.y, 0.f);
                float f6 = fmaxf(x1.z + y1.z, 0.f), f7 = fmaxf(x1.w + y1.w, 0.f);
                __nv_bfloat162 h0 = __float22bfloat162_rn(make_float2(f0, f1));
                __nv_bfloat162 h1 = __float22bfloat162_rn(make_float2(f2, f3));
                __nv_bfloat162 h2 = __float22bfloat162_rn(make_float2(f4, f5));
                __nv_bfloat162 h3 = __float22bfloat162_rn(make_float2(f6, f7));
                ua[q].x = *reinterpret_cast<unsigned*>(&h0);
                ua[q].y = *reinterpret_cast<unsigned*>(&h1);
                ua[q].z = *reinterpret_cast<unsigned*>(&h2);
                ua[q].w = *reinterpret_cast<unsigned*>(&h3);
            }
        }
        ub = *reinterpret_cast<const uint4*>(Bw + (size_t)(col0 + br) * K + kt + bc);
    };

    fetch(0);
    int w = tid >> 5, wm = w & 3, wn = w >> 2, l = tid & 31;
    int lr = l >> 2, lc = (l & 3) * 2;

    for (int kt = 0; kt < K; kt += BK) {
        __syncthreads();
        *reinterpret_cast<uint4*>(&As[ar[0] * LDA + ac[0]]) = ua[0];
        *reinterpret_cast<uint4*>(&As[ar[1] * LDA + ac[1]]) = ua[1];
        *reinterpret_cast<uint4*>(&Bs[br * LDA + bc]) = ub;
        __syncthreads();
        if (kt + BK < K) fetch(kt + BK);

        #pragma unroll
        for (int s = 0; s < 2; s++) {
            int k0 = s * 16;
            unsigned a[2][4], b[4][2];
            #pragma unroll
            for (int i = 0; i < 2; i++) {
                const __nv_bfloat16* p = &As[(wm * 32 + i * 16 + lr) * LDA + k0 + lc];
                a[i][0] = *reinterpret_cast<const unsigned*>(p);
                a[i][1] = *reinterpret_cast<const unsigned*>(p + 8 * LDA);
                a[i][2] = *reinterpret_cast<const unsigned*>(p + 8);
                a[i][3] = *reinterpret_cast<const unsigned*>(p + 8 * LDA + 8);
            }
            #pragma unroll
            for (int j = 0; j < 4; j++) {
                const __nv_bfloat16* p = &Bs[(wn * 32 + j * 8 + lr) * LDA + k0 + lc];
                b[j][0] = *reinterpret_cast<const unsigned*>(p);
                b[j][1] = *reinterpret_cast<const unsigned*>(p + 8);
            }
            #pragma unroll
            for (int i = 0; i < 2; i++)
                #pragma unroll
                for (int j = 0; j < 4; j++)
                    asm volatile(
                        "mma.sync.aligned.m16n8k16.row.col.f32.bf16.bf16.f32 "
                        "{%0,%1,%2,%3},{%4,%5,%6,%7},{%8,%9},{%0,%1,%2,%3};"
                        : "+f"(acc[i][j][0]), "+f"(acc[i][j][1]),
                          "+f"(acc[i][j][2]), "+f"(acc[i][j][3])
                        : "r"(a[i][0]), "r"(a[i][1]), "r"(a[i][2]), "r"(a[i][3]),
                          "r"(b[j][0]), "r"(b[j][1]));
        }
    }

    // epilogue
    #pragma unroll
    for (int i = 0; i < 2; i++) {
        int m = row0 + wm * 32 + i * 16 + lr;
        #pragma unroll
        for (int j = 0; j < 4; j++) {
            int col = col0 + wn * 32 + j * 8 + lc;
            float b0 = bias[col], b1 = bias[col + 1];
            float v0 = acc[i][j][0] + b0, v1 = acc[i][j][1] + b1;
            float v2 = acc[i][j][2] + b0, v3 = acc[i][j][3] + b1;
            if (RELU) {
                v0 = fmaxf(v0, 0.f); v1 = fmaxf(v1, 0.f);
                v2 = fmaxf(v2, 0.f); v3 = fmaxf(v3, 0.f);
            }
            if (OUTB) {
                __nv_bfloat162 p0 = __float22bfloat162_rn(make_float2(v0, v1));
                __nv_bfloat162 p1 = __float22bfloat162_rn(make_float2(v2, v3));
                *reinterpret_cast<__nv_bfloat162*>(Cb + (size_t)m * N + col) = p0;
                *reinterpret_cast<__nv_bfloat162*>(Cb + (size_t)(m + 8) * N + col) = p1;
            } else {
                *reinterpret_cast<float2*>(Cf + (size_t)m * N + col) = make_float2(v0, v1);
                *reinterpret_cast<float2*>(Cf + (size_t)(m + 8) * N + col) = make_float2(v2, v3);
            }
        }
    }
}

// ---------------------------------------------------------------------------
// K3: LSTM recurrence on tensor cores, 4-CTA cluster, 2 batches per cluster.
// R10 winner structure (per-step hardware cluster.sync), with the R11 data
// trims: bf16 x-projection input, bf16-only y output.
// CTA rank owns CTA-local gates n = 0..255 (gate g = n>>6, j = j0 + (n&63));
// Whh slice in 128 B-fragment registers/thread. Per step:
// z[16,256] = h[16,256] @ W^T via mma.m16n8k16; A rows 0,1 = two batches' h.
// Owners use MUFU activations; h broadcast via DSMEM; double-buffered hA.
// ---------------------------------------------------------------------------
__global__ void __cluster_dims__(4, 1, 1) __launch_bounds__(256, 1)
lstm_mma_kernel(const __nv_bfloat16* __restrict__ xw,
                const float* __restrict__ whh_l,   // fp32 [2][G4][HID]
                __nv_bfloat16* __restrict__ yb) {
    __shared__ __align__(16) __nv_bfloat16 hA[2][2][264];  // [par][batch][k]
    __shared__ __align__(16) float zs[2][260];             // [batch][n]

    int tid = threadIdx.x;
    int w = tid >> 5, l = tid & 31;
    int gq = l >> 2, t2 = (l & 3) * 2;
    int rank = blockIdx.x & 3;
    int cid  = blockIdx.x >> 2;
    int dir  = cid >> 4;
    int bp   = cid & 15;
    int j0   = rank * 64;

    // zero h staging (both parities)
    for (int i = tid; i < 2 * 2 * 264; i += 256)
        (&hA[0][0][0])[i] = __float2bfloat16(0.f);

    // ---- B-fragment preload: W[n][k] resident in registers ----------------
    unsigned Bf[4][16][2];
    {
        const float* wd = whh_l + (size_t)dir * G4 * HID;
        #pragma unroll
        for (int nt = 0; nt < 4; nt++) {
            int n = w * 32 + nt * 8 + gq;            // CTA-local gate index
            int g = n >> 6, jl = n & 63;
            const float* wp = wd + (size_t)(g * 256 + j0 + jl) * HID;
            #pragma unroll
            for (int kt = 0; kt < 16; kt++) {
                int k0 = kt * 16 + t2;
                float2 wa = *reinterpret_cast<const float2*>(wp + k0);
                float2 wb = *reinterpret_cast<const float2*>(wp + k0 + 8);
                __nv_bfloat162 qa = __float22bfloat162_rn(wa);
                __nv_bfloat162 qb = __float22bfloat162_rn(wb);
                Bf[nt][kt][0] = *reinterpret_cast<unsigned*>(&qa);
                Bf[nt][kt][1] = *reinterpret_cast<unsigned*>(&qb);
            }
        }
    }
    __syncthreads();
    asm volatile("barrier.cluster.arrive.aligned;" ::: "memory");
    asm volatile("barrier.cluster.wait.aligned;" ::: "memory");

    int bg0 = bp * 2;
    const __nv_bfloat16* xd = xw + (size_t)dir * MBT * G4;
    int xcol = (w >> 1) * 256 + j0 + (w & 1) * 32;   // global z-col base
    int brow = gq & 1;                               // A-row (= batch) for lanes 0-7

    // owner mapping: tid<64 -> j = tid (both batches)
    int jg = j0 + tid;
    size_t y0off = (size_t)bg0 * SEQT * DMOD + dir * HID + jg;
    size_t y1off = y0off + (size_t)SEQT * DMOD;
    float c0 = 0.f, c1 = 0.f;

    unsigned hAbase;
    asm("{ .reg .u64 t; cvta.to.shared.u64 t, %1; cvt.u32.u64 %0, t; }"
        : "=r"(hAbase) : "l"(&hA[0][0][0]));

    // first step's x (accumulator init values, lanes 0-7)
    float2 xi[4];
    {
        int t0 = dir ? SEQT - 1 : 0;
        #pragma unroll
        for (int nt = 0; nt < 4; nt++) {
            xi[nt] = make_float2(0.f, 0.f);
            if (l < 8) {
                __nv_bfloat162 u = *reinterpret_cast<const __nv_bfloat162*>(
                    xd + ((size_t)(bg0 + brow) * SEQT + t0) * G4 + xcol + nt * 8 + t2);
                xi[nt] = __bfloat1622float2(u);
            }
        }
    }

    unsigned zc = 0u;
    int par = 0;
    for (int s = 0; s < SEQT; s++) {
        int t = dir ? (SEQT - 1 - s) : s;

        // prefetch next step's x
        int sn = (s + 1 < SEQT) ? s + 1 : s;
        int tn = dir ? (SEQT - 1 - sn) : sn;
        float2 xn[4];
        #pragma unroll
        for (int nt = 0; nt < 4; nt++) {
            xn[nt] = make_float2(0.f, 0.f);
            if (l < 8) {
                __nv_bfloat162 u = *reinterpret_cast<const __nv_bfloat162*>(
                    xd + ((size_t)(bg0 + brow) * SEQT + tn) * G4 + xcol + nt * 8 + t2);
                xn[nt] = __bfloat1622float2(u);
            }
        }

        // accumulators = x (bias folded); rows 8,9 unused -> 0
        float acc[4][4];
        #pragma unroll
        for (int nt = 0; nt < 4; nt++) {
            acc[nt][0] = xi[nt].x; acc[nt][1] = xi[nt].y;
            acc[nt][2] = 0.f;      acc[nt][3] = 0.f;
        }

        // mma over k = 256 (16 tiles)
        const __nv_bfloat16* hrow = &hA[par][brow][0];
        #pragma unroll
        for (int kt = 0; kt < 16; kt++) {
            unsigned a0 = 0u, a2 = 0u;
            if (l < 8) {
                a0 = *reinterpret_cast<const unsigned*>(hrow + kt * 16 + t2);
                a2 = *reinterpret_cast<const unsigned*>(hrow + kt * 16 + t2 + 8);
            }
            #pragma unroll
            for (int nt = 0; nt < 4; nt++)
                asm volatile(
                    "mma.sync.aligned.m16n8k16.row.col.f32.bf16.bf16.f32 "
                    "{%0,%1,%2,%3},{%4,%5,%6,%7},{%8,%9},{%0,%1,%2,%3};"
                    : "+f"(acc[nt][0]), "+f"(acc[nt][1]),
                      "+f"(acc[nt][2]), "+f"(acc[nt][3])
                    : "r"(a0), "r"(zc), "r"(a2), "r"(zc),
                      "r"(Bf[nt][kt][0]), "r"(Bf[nt][kt][1]));
        }

        // z -> smem (lanes 0-7 hold rows 0,1)
        if (l < 8) {
            #pragma unroll
            for (int nt = 0; nt < 4; nt++)
                *reinterpret_cast<float2*>(&zs[brow][w * 32 + nt * 8 + t2]) =
                    make_float2(acc[nt][0], acc[nt][1]);
        }
        __syncthreads();

        // owners: MUFU activations + bf16 y + DSMEM broadcast
        if (tid < 64) {
            float z0[4], z1[4];
            #pragma unroll
            for (int g = 0; g < 4; g++) {
                z0[g] = zs[0][g * 64 + tid];
                z1[g] = zs[1][g * 64 + tid];
            }
            c0 = sigm_a(z0[1]) * c0 + sigm_a(z0[0]) * tanh_a(z0[2]);
            float h0 = sigm_a(z0[3]) * tanh_a(c0);
            c1 = sigm_a(z1[1]) * c1 + sigm_a(z1[0]) * tanh_a(z1[2]);
            float h1 = sigm_a(z1[3]) * tanh_a(c1);
            __nv_bfloat16 hb0 = __float2bfloat16(h0);
            __nv_bfloat16 hb1 = __float2bfloat16(h1);
            yb[y0off + (size_t)t * DMOD] = hb0;
            yb[y1off + (size_t)t * DMOD] = hb1;

            unsigned u0 = (unsigned)__bfloat16_as_ushort(hb0);
            unsigned u1 = (unsigned)__bfloat16_as_ushort(hb1);
            unsigned n0 = __shfl_down_sync(0xffffffffu, u0, 1);
            unsigned n1 = __shfl_down_sync(0xffffffffu, u1, 1);
            if (!(tid & 1)) {
                unsigned pk0 = u0 | (n0 << 16);
                unsigned pk1 = u1 | (n1 << 16);
                unsigned d0 = hAbase + (unsigned)((((par ^ 1) * 2 + 0) * 264 + jg) * 2);
                unsigned d1 = d0 + 264u * 2u;
                #pragma unroll
                for (int r = 0; r < 4; r++) {
                    asm volatile(
                        "{ .reg .b32 ra; mapa.shared::cluster.u32 ra, %0, %1; "
                        "st.shared::cluster.b32 [ra], %2; }"
                        :: "r"(d0), "r"(r), "r"(pk0) : "memory");
                    asm volatile(
                        "{ .reg .b32 ra; mapa.shared::cluster.u32 ra, %0, %1; "
                        "st.shared::cluster.b32 [ra], %2; }"
                        :: "r"(d1), "r"(r), "r"(pk1) : "memory");
                }
            }
        }
        asm volatile("barrier.cluster.arrive.aligned;" ::: "memory");
        asm volatile("barrier.cluster.wait.aligned;" ::: "memory");

        par ^= 1;
        #pragma unroll
        for (int nt = 0; nt < 4; nt++) xi[nt] = xn[nt];
    }
}

// ---------------------------------------------------------------------------
// K4: zero cont + mask
// ---------------------------------------------------------------------------
__global__ void zero_kernel() {
    int idx = blockIdx.x * blockDim.x + threadIdx.x;
    const int NC4 = (MENT * DMOD) / 4;
    if (idx < NC4) reinterpret_cast<float4*>(g_cont)[idx] = make_float4(0, 0, 0, 0);
    if (idx < MENT / 4) reinterpret_cast<float4*>(g_mask)[idx] = make_float4(0, 0, 0, 0);
}

// ---------------------------------------------------------------------------
// K5: ragged span mean-pool + scatter-add (atomic); reads bf16 activations
// ---------------------------------------------------------------------------
__global__ void span_pool_kernel(const __nv_bfloat16* __restrict__ x) {
    int be = blockIdx.x;
    int b = be >> 6;
    const int* ei = g_ent + be * 3;
    int id = ei[0], st = ei[1], en = ei[2];
    if (id < 0 || id >= ENT) return;
    int lo = st, hi = en;
    float sgn = 1.f;
    if (en < st) { lo = en; hi = st; sgn = -1.f; }
    lo = max(lo, 0); hi = min(hi, SEQT);
    float len = (float)max(en - st, 1);

    int d = threadIdx.x;                 // 128 lanes, 4 bf16 each
    float4 acc = make_float4(0, 0, 0, 0);
    const uint2* xp =
        reinterpret_cast<const uint2*>(x + (size_t)b * SEQT * DMOD) + d;
    for (int t = lo; t < hi; t++) {
        uint2 u = xp[(size_t)t * (DMOD / 4)];
        float2 a = __bfloat1622float2(*reinterpret_cast<__nv_bfloat162*>(&u.x));
        float2 bb = __bfloat1622float2(*reinterpret_cast<__nv_bfloat162*>(&u.y));
        acc.x += a.x; acc.y += a.y; acc.z += bb.x; acc.w += bb.y;
    }
    float invl = sgn / len;
    float* cp = g_cont + ((size_t)(b * ENT + id)) * DMOD + d * 4;
    atomicAdd(cp + 0, acc.x * invl);
    atomicAdd(cp + 1, acc.y * invl);
    atomicAdd(cp + 2, acc.z * invl);
    atomicAdd(cp + 3, acc.w * invl);
    if (d == 0) atomicAdd(&g_mask[b * ENT + id], 1.f);
}

// ---------------------------------------------------------------------------
// K6: LayerNorm over D=512 -> fp32 cw
// ---------------------------------------------------------------------------
__global__ __launch_bounds__(256)
void ln_kernel(const float* __restrict__ gw, const float* __restrict__ gb) {
    int row = blockIdx.x;
    int tid = threadIdx.x;
    const float* xr = g_cont + (size_t)row * DMOD;
    float v0 = xr[tid], v1 = xr[tid + 256];

    __shared__ float red[8];
    __shared__ float bc;
    int lane = tid & 31, warp = tid >> 5;

    float s = v0 + v1;
    #pragma unroll
    for (int o = 16; o; o >>= 1) s += __shfl_xor_sync(0xffffffffu, s, o);
    if (lane == 0) red[warp] = s;
    __syncthreads();
    if (tid == 0) {
        float t = 0;
        #pragma unroll
        for (int w = 0; w < 8; w++) t += red[w];
        bc = t * (1.f / DMOD);
    }
    __syncthreads();
    float mu = bc;
    __syncthreads();

    float d0 = v0 - mu, d1 = v1 - mu;
    float q = d0 * d0 + d1 * d1;
    #pragma unroll
    for (int o = 16; o; o >>= 1) q += __shfl_xor_sync(0xffffffffu, q, o);
    if (lane == 0) red[warp] = q;
    __syncthreads();
    if (tid == 0) {
        float t = 0;
        #pragma unroll
        for (int w = 0; w < 8; w++) t += red[w];
        bc = t * (1.f / DMOD);
    }
    __syncthreads();
    float inv = rsqrtf(bc + 1e-5f);

    float* o = g_cw + (size_t)row * DMOD;
    o[tid]       = d0 * inv * gw[tid]       + gb[tid];
    o[tid + 256] = d1 * inv * gw[tid + 256] + gb[tid + 256];
}

// ---------------------------------------------------------------------------
// K7: mask + log_softmax over R=64 (one warp per row, in-place on d_out)
// ---------------------------------------------------------------------------
__global__ __launch_bounds__(256)
void lsm_kernel(float* __restrict__ out) {
    int warp = threadIdx.x >> 5, lane = threadIdx.x & 31;
    int row = blockIdx.x * 8 + warp;
    int b = row >> 12, i = (row >> 6) & 63, j = row & 63;
    float m = fminf(g_mask[b * ENT + i], 1.f) * fminf(g_mask[b * ENT + j], 1.f);
    float* p = out + (size_t)row * REL;
    float v0 = p[lane] * m, v1 = p[lane + 32] * m;
    float mx = fmaxf(v0, v1);
    #pragma unroll
    for (int o = 16; o; o >>= 1) mx = fmaxf(mx, __shfl_xor_sync(0xffffffffu, mx, o));
    float s = expf(v0 - mx) + expf(v1 - mx);
    #pragma unroll
    for (int o = 16; o; o >>= 1) s += __shfl_xor_sync(0xffffffffu, s, o);
    float lse = mx + logf(s);
    p[lane] = v0 - lse;
    p[lane + 32] = v1 - lse;
}

// ---------------------------------------------------------------------------
// Host launch
// ---------------------------------------------------------------------------
extern "C" void kernel_launch(void* const* d_in, const int* in_sizes, int n_in,
                              void* d_out, int out_size) {
    int off = (in_sizes[2] == 1) ? 0 : -1;
    const unsigned* sents_raw = (const unsigned*)d_in[0];
    const unsigned* ent_raw   = (const unsigned*)d_in[1];
    const float* emb    = (const float*)d_in[3 + off];
    const float* Wih    = (const float*)d_in[4 + off];
    const float* Whh    = (const float*)d_in[5 + off];
    const float* bih    = (const float*)d_in[6 + off];
    const float* bhh    = (const float*)d_in[7 + off];
    const float* ln_g   = (const float*)d_in[8 + off];
    const float* ln_b   = (const float*)d_in[9 + off];
    const float* rel1_w = (const float*)d_in[10 + off];
    const float* rel1_b = (const float*)d_in[11 + off];
    const float* rel2_w = (const float*)d_in[12 + off];
    const float* rel2_b = (const float*)d_in[13 + off];
    const float* proj_w = (const float*)d_in[14 + off];
    const float* proj_b = (const float*)d_in[15 + off];
    const float* dec_w  = (const float*)d_in[16 + off];
    const float* dec_b  = (const float*)d_in[17 + off];
    float* out = (float*)d_out;

    float *p_bias, *p_cw, *p_r1, *p_r2;
    __nv_bfloat16 *p_xb, *p_xwb, *p_cwb, *p_Tb, *p_wihb, *p_r1b, *p_r2b, *p_pjb, *p_dcb;
    cudaGetSymbolAddress((void**)&p_bias, g_bias);
    cudaGetSymbolAddress((void**)&p_cw, g_cw);
    cudaGetSymbolAddress((void**)&p_r1, g_rel1);
    cudaGetSymbolAddress((void**)&p_r2, g_rel2);
    cudaGetSymbolAddress((void**)&p_xb, g_xb);
    cudaGetSymbolAddress((void**)&p_xwb, g_xwb);
    cudaGetSymbolAddress((void**)&p_cwb, g_cwb);
    cudaGetSymbolAddress((void**)&p_Tb, g_Tb);
    cudaGetSymbolAddress((void**)&p_wihb, g_wihb);
    cudaGetSymbolAddress((void**)&p_r1b, g_r1b);
    cudaGetSymbolAddress((void**)&p_r2b, g_r2b);
    cudaGetSymbolAddress((void**)&p_pjb, g_pjb);
    cudaGetSymbolAddress((void**)&p_dcb, g_dcb);

    prep_idx_kernel<<<1, 256>>>(sents_raw, ent_raw);
    prep_bias_kernel<<<16, 256>>>(bih, bhh);
    f2b_kernel<<<2048, 256>>>(Wih, p_wihb, NLAY * 2 * G4 * DMOD / 4);
    f2b_kernel<<<256, 256>>>(rel1_w, p_r1b, DMOD * DMOD / 4);
    f2b_kernel<<<256, 256>>>(rel2_w, p_r2b, DMOD * DMOD / 4);
    f2b_kernel<<<256, 256>>>(proj_w, p_pjb, DMOD * DMOD / 4);
    f2b_kernel<<<32, 256>>>(dec_w, p_dcb, REL * DMOD / 4);
    embed_kernel<<<MBT, 128>>>(emb);

    for (int l = 0; l < NLAY; l++) {
        // both directions in one launch (gridDim.z = 2), bf16 output
        hgemm_nt<false, true, false><<<dim3(G4 / 64, MBT / 128, 2), 256>>>(
            p_xb, p_wihb + (size_t)(l * 2) * G4 * DMOD,
            p_bias + (l * 2) * G4,
            nullptr, p_xwb,
            MBT, G4, DMOD, nullptr, nullptr,
            (size_t)G4 * DMOD, (size_t)G4, (size_t)MBT * G4);
        // writes bf16 y into g_xb (next layer's input / final pooling source)
        lstm_mma_kernel<<<128, 256>>>(
            p_xwb, Whh + (size_t)l * 2 * G4 * HID, p_xb);
    }

    zero_kernel<<<1024, 256>>>();
    span_pool_kernel<<<MENT, 128>>>(p_xb);
    ln_kernel<<<MENT, 256>>>(ln_g, ln_b);
    f2b_kernel<<<(MENT * DMOD / 4 + 255) / 256, 256>>>(p_cw, p_cwb, MENT * DMOD / 4);

    hgemm_nt<false, false, false><<<dim3(DMOD / 64, MENT / 128), 256>>>(
        p_cwb, p_r1b, rel1_b, p_r1, nullptr, MENT, DMOD, DMOD, nullptr, nullptr,
        0, 0, 0);
    hgemm_nt<false, false, false><<<dim3(DMOD / 64, MENT / 128), 256>>>(
        p_cwb, p_r2b, rel2_b, p_r2, nullptr, MENT, DMOD, DMOD, nullptr, nullptr,
        0, 0, 0);

    // pairwise: Tb = relu( relu(r1_j + r2_i) @ proj_w.T + proj_b )  (bf16 out)
    hgemm_nt<true, true, true><<<dim3(DMOD / 64, MPAIR / 128), 256>>>(
        nullptr, p_pjb, proj_b, nullptr, p_Tb, MPAIR, DMOD, DMOD, p_r1, p_r2,
        0, 0, 0);

    // logits = Tb @ dec_w.T + dec_b  -> d_out (fp32)
    hgemm_nt<false, false, false><<<dim3(REL / 64, MPAIR / 128), 256>>>(
        p_Tb, p_dcb, dec_b, out, nullptr, MPAIR, REL, DMOD, nullptr, nullptr,
        0, 0, 0);

    lsm_kernel<<<MPAIR / 8, 256>>>(out);
}

// round 13
// speedup vs baseline: 1.3313x; 1.2647x over previous
#include <cuda_runtime.h>
#include <cuda_bf16.h>
#include <cstddef>

// ---------------------------------------------------------------------------
// Problem constants
// ---------------------------------------------------------------------------
#define BATCH 32
#define SEQT  512
#define DMOD  512
#define HID   256
#define G4    1024          // 4*HID
#define ENT   64
#define REL   64
#define NLAY  2
#define MBT   (BATCH*SEQT)          // 16384 token rows
#define MPAIR (BATCH*ENT*ENT)       // 131072 pair rows
#define MENT  (BATCH*ENT)           // 2048 entity rows

// ---------------------------------------------------------------------------
// Device scratch (static allocation only — no cudaMalloc allowed)
// ---------------------------------------------------------------------------
__device__ __nv_bfloat16  g_xb[(size_t)MBT * DMOD];        // bf16 activations
__device__ float          g_xw[(size_t)2 * MBT * G4];      // per-dir input proj (fp32)
__device__ float          g_bias[NLAY * 2 * G4];           // bih+bhh
__device__ int            g_sents[MBT];
__device__ int            g_ent[MENT * 3];
__device__ float          g_cont[(size_t)MENT * DMOD];
__device__ float          g_mask[MENT];
__device__ float          g_cw[(size_t)MENT * DMOD];
__device__ __nv_bfloat16  g_cwb[(size_t)MENT * DMOD];
__device__ float          g_rel1[(size_t)MENT * DMOD];
__device__ float          g_rel2[(size_t)MENT * DMOD];
__device__ __nv_bfloat16  g_Tb[(size_t)MPAIR * DMOD];      // pair hidden, bf16
// bf16 weight copies
__device__ __nv_bfloat16  g_wihb[(size_t)NLAY * 2 * G4 * DMOD];
__device__ __nv_bfloat16  g_r1b[DMOD * DMOD];
__device__ __nv_bfloat16  g_r2b[DMOD * DMOD];
__device__ __nv_bfloat16  g_pjb[DMOD * DMOD];
__device__ __nv_bfloat16  g_dcb[REL * DMOD];

__device__ __forceinline__ float tanh_a(float x) {
    float r;
    asm("tanh.approx.f32 %0, %1;" : "=f"(r) : "f"(x));
    return r;
}
__device__ __forceinline__ float sigm_a(float x) {
    return fmaf(tanh_a(0.5f * x), 0.5f, 0.5f);
}

// ---------------------------------------------------------------------------
// K0: canonicalize sents / ent_inds (int64-or-int32 auto-detect) -> int32
// ---------------------------------------------------------------------------
__global__ void prep_idx_kernel(const unsigned* __restrict__ sents_raw,
                                const unsigned* __restrict__ ent_raw) {
    __shared__ int s64f, e64f;
    int tid = threadIdx.x;
    if (tid == 0) {
        bool s64 = true;
        for (int i = 0; i < 64; i++)
            if (sents_raw[2 * i + 1] != 0u) { s64 = false; break; }
        bool e64 = true;
        for (int i = 0; i < 64; i++) {
            unsigned lo = ent_raw[2 * i], hi = ent_raw[2 * i + 1];
            unsigned expct = ((int)lo < 0) ? 0xFFFFFFFFu : 0u;
            if (hi != expct) { e64 = false; break; }
        }
        s64f = s64; e64f = e64;
    }
    __syncthreads();
    int s64 = s64f, e64 = e64f;
    for (int i = tid; i < MBT; i += blockDim.x)
        g_sents[i] = s64 ? (int)sents_raw[2 * i] : (int)sents_raw[i];
    for (int i = tid; i < MENT * 3; i += blockDim.x)
        g_ent[i] = e64 ? (int)ent_raw[2 * i] : (int)ent_raw[i];
}

__global__ void prep_bias_kernel(const float* __restrict__ bih,
                                 const float* __restrict__ bhh) {
    int i = blockIdx.x * blockDim.x + threadIdx.x;
    if (i < NLAY * 2 * G4) g_bias[i] = bih[i] + bhh[i];
}

// ---------------------------------------------------------------------------
// f32 -> bf16 vectorized convert (n4 float4-groups)
// ---------------------------------------------------------------------------
__global__ void f2b_kernel(const float* __restrict__ src,
                           __nv_bfloat16* __restrict__ dst, int n4) {
    int i = blockIdx.x * blockDim.x + threadIdx.x;
    if (i >= n4) return;
    float4 v = reinterpret_cast<const float4*>(src)[i];
    __nv_bfloat162 lo = __float22bfloat162_rn(make_float2(v.x, v.y));
    __nv_bfloat162 hi = __float22bfloat162_rn(make_float2(v.z, v.w));
    uint2 u;
    u.x = *reinterpret_cast<unsigned*>(&lo);
    u.y = *reinterpret_cast<unsigned*>(&hi);
    reinterpret_cast<uint2*>(dst)[i] = u;
}

// ---------------------------------------------------------------------------
// K2: embedding gather -> bf16 activations
// ---------------------------------------------------------------------------
__global__ void embed_kernel(const float* __restrict__ emb) {
    int row = blockIdx.x;
    int d = threadIdx.x;                               // 128 float4 lanes
    int tok = g_sents[row];
    float4 v = reinterpret_cast<const float4*>(emb + (size_t)tok * DMOD)[d];
    __nv_bfloat162 lo = __float22bfloat162_rn(make_float2(v.x, v.y));
    __nv_bfloat162 hi = __float22bfloat162_rn(make_float2(v.z, v.w));
    uint2 u;
    u.x = *reinterpret_cast<unsigned*>(&lo);
    u.y = *reinterpret_cast<unsigned*>(&hi);
    reinterpret_cast<uint2*>(g_xb + (size_t)row * DMOD)[d] = u;
}

// ---------------------------------------------------------------------------
// bf16 tensor-core GEMM: C[M,N] = A[M,K] @ W[N,K]^T + bias, fp32 accum.
// BM=128 BN=64 BK=32, 256 thr (8 warps, 4x2), warp tile 32x32 via mma.m16n8k16.
// GEN: A generated on the fly as relu(r1[b,j]+r2[b,i]); OUTB: bf16 output.
// ---------------------------------------------------------------------------
template <bool GEN, bool OUTB, bool RELU>
__global__ __launch_bounds__(256)
void hgemm_nt(const __nv_bfloat16* __restrict__ A,
              const __nv_bfloat16* __restrict__ Bw,
              const float* __restrict__ bias,
              float* __restrict__ Cf, __nv_bfloat16* __restrict__ Cb,
              int M, int N, int K,
              const float* __restrict__ r1, const float* __restrict__ r2) {
    const int BM = 128, BN = 64, BK = 32, LDA = BK + 8;
    __shared__ __align__(16) __nv_bfloat16 As[BM * LDA];
    __shared__ __align__(16) __nv_bfloat16 Bs[BN * LDA];
    int tid = threadIdx.x;
    int row0 = blockIdx.y * BM, col0 = blockIdx.x * BN;

    int ar[2], ac[2];
    #pragma unroll
    for (int q = 0; q < 2; q++) {
        int idx = tid + q * 256;
        ar[q] = idx >> 2;
        ac[q] = (idx & 3) * 8;
    }
    int br = tid >> 2, bc = (tid & 3) * 8;

    float acc[2][4][4];
    #pragma unroll
    for (int i = 0; i < 2; i++)
        #pragma unroll
        for (int j = 0; j < 4; j++)
            #pragma unroll
            for (int c = 0; c < 4; c++) acc[i][j][c] = 0.f;

    uint4 ua[2], ub;
    auto fetch = [&](int kt) {
        #pragma unroll
        for (int q = 0; q < 2; q++) {
            int m = row0 + ar[q];
            if (!GEN) {
                ua[q] = *reinterpret_cast<const uint4*>(A + (size_t)m * K + kt + ac[q]);
            } else {
                int bb = m >> 12, ii = (m >> 6) & 63, jj = m & 63;
                const float4* p1 = reinterpret_cast<const float4*>(
                    r1 + ((size_t)(bb * ENT + jj)) * DMOD + kt + ac[q]);
                const float4* p2 = reinterpret_cast<const float4*>(
                    r2 + ((size_t)(bb * ENT + ii)) * DMOD + kt + ac[q]);
                float4 x0 = p1[0], x1 = p1[1], y0 = p2[0], y1 = p2[1];
                float f0 = fmaxf(x0.x + y0.x, 0.f), f1 = fmaxf(x0.y + y0.y, 0.f);
                float f2 = fmaxf(x0.z + y0.z, 0.f), f3 = fmaxf(x0.w + y0.w, 0.f);
                float f4 = fmaxf(x1.x + y1.x, 0.f), f5 = fmaxf(x1.y + y1.y, 0.f);
                float f6 = fmaxf(x1.z + y1.z, 0.f), f7 = fmaxf(x1.w + y1.w, 0.f);
                __nv_bfloat162 h0 = __float22bfloat162_rn(make_float2(f0, f1));
                __nv_bfloat162 h1 = __float22bfloat162_rn(make_float2(f2, f3));
                __nv_bfloat162 h2 = __float22bfloat162_rn(make_float2(f4, f5));
                __nv_bfloat162 h3 = __float22bfloat162_rn(make_float2(f6, f7));
                ua[q].x = *reinterpret_cast<unsigned*>(&h0);
                ua[q].y = *reinterpret_cast<unsigned*>(&h1);
                ua[q].z = *reinterpret_cast<unsigned*>(&h2);
                ua[q].w = *reinterpret_cast<unsigned*>(&h3);
            }
        }
        ub = *reinterpret_cast<const uint4*>(Bw + (size_t)(col0 + br) * K + kt + bc);
    };

    fetch(0);
    int w = tid >> 5, wm = w & 3, wn = w >> 2, l = tid & 31;
    int lr = l >> 2, lc = (l & 3) * 2;

    for (int kt = 0; kt < K; kt += BK) {
        __syncthreads();
        *reinterpret_cast<uint4*>(&As[ar[0] * LDA + ac[0]]) = ua[0];
        *reinterpret_cast<uint4*>(&As[ar[1] * LDA + ac[1]]) = ua[1];
        *reinterpret_cast<uint4*>(&Bs[br * LDA + bc]) = ub;
        __syncthreads();
        if (kt + BK < K) fetch(kt + BK);

        #pragma unroll
        for (int s = 0; s < 2; s++) {
            int k0 = s * 16;
            unsigned a[2][4], b[4][2];
            #pragma unroll
            for (int i = 0; i < 2; i++) {
                const __nv_bfloat16* p = &As[(wm * 32 + i * 16 + lr) * LDA + k0 + lc];
                a[i][0] = *reinterpret_cast<const unsigned*>(p);
                a[i][1] = *reinterpret_cast<const unsigned*>(p + 8 * LDA);
                a[i][2] = *reinterpret_cast<const unsigned*>(p + 8);
                a[i][3] = *reinterpret_cast<const unsigned*>(p + 8 * LDA + 8);
            }
            #pragma unroll
            for (int j = 0; j < 4; j++) {
                const __nv_bfloat16* p = &Bs[(wn * 32 + j * 8 + lr) * LDA + k0 + lc];
                b[j][0] = *reinterpret_cast<const unsigned*>(p);
                b[j][1] = *reinterpret_cast<const unsigned*>(p + 8);
            }
            #pragma unroll
            for (int i = 0; i < 2; i++)
                #pragma unroll
                for (int j = 0; j < 4; j++)
                    asm volatile(
                        "mma.sync.aligned.m16n8k16.row.col.f32.bf16.bf16.f32 "
                        "{%0,%1,%2,%3},{%4,%5,%6,%7},{%8,%9},{%0,%1,%2,%3};"
                        : "+f"(acc[i][j][0]), "+f"(acc[i][j][1]),
                          "+f"(acc[i][j][2]), "+f"(acc[i][j][3])
                        : "r"(a[i][0]), "r"(a[i][1]), "r"(a[i][2]), "r"(a[i][3]),
                          "r"(b[j][0]), "r"(b[j][1]));
        }
    }

    // epilogue
    #pragma unroll
    for (int i = 0; i < 2; i++) {
        int m = row0 + wm * 32 + i * 16 + lr;
        #pragma unroll
        for (int j = 0; j < 4; j++) {
            int col = col0 + wn * 32 + j * 8 + lc;
            float b0 = bias[col], b1 = bias[col + 1];
            float v0 = acc[i][j][0] + b0, v1 = acc[i][j][1] + b1;
            float v2 = acc[i][j][2] + b0, v3 = acc[i][j][3] + b1;
            if (RELU) {
                v0 = fmaxf(v0, 0.f); v1 = fmaxf(v1, 0.f);
                v2 = fmaxf(v2, 0.f); v3 = fmaxf(v3, 0.f);
            }
            if (OUTB) {
                __nv_bfloat162 p0 = __float22bfloat162_rn(make_float2(v0, v1));
                __nv_bfloat162 p1 = __float22bfloat162_rn(make_float2(v2, v3));
                *reinterpret_cast<__nv_bfloat162*>(Cb + (size_t)m * N + col) = p0;
                *reinterpret_cast<__nv_bfloat162*>(Cb + (size_t)(m + 8) * N + col) = p1;
            } else {
                *reinterpret_cast<float2*>(Cf + (size_t)m * N + col) = make_float2(v0, v1);
                *reinterpret_cast<float2*>(Cf + (size_t)(m + 8) * N + col) = make_float2(v2, v3);
            }
        }
    }
}

// ---------------------------------------------------------------------------
// K3: LSTM recurrence on tensor cores, 4-CTA cluster, 2 batches per cluster.
// R10 winner structure (fp32 x-projection, per-step hardware cluster.sync,
// 128 B-fragment registers/thread) with a widened owner phase:
// 128 owner threads (batch = tid>>6, j = tid&63), each running ONE
// activation chain; pairs pack bf16 h and broadcast via DSMEM; the cluster
// arrive is hoisted before the y global store so the STG retires inside the
// barrier window. y is written bf16-only.
// ---------------------------------------------------------------------------
__global__ void __cluster_dims__(4, 1, 1) __launch_bounds__(256, 1)
lstm_mma_kernel(const float* __restrict__ xw,
                const float* __restrict__ whh_l,   // fp32 [2][G4][HID]
                __nv_bfloat16* __restrict__ yb) {
    __shared__ __align__(16) __nv_bfloat16 hA[2][2][264];  // [par][batch][k]
    __shared__ __align__(16) float zs[2][260];             // [batch][n]

    int tid = threadIdx.x;
    int w = tid >> 5, l = tid & 31;
    int gq = l >> 2, t2 = (l & 3) * 2;
    int rank = blockIdx.x & 3;
    int cid  = blockIdx.x >> 2;
    int dir  = cid >> 4;
    int bp   = cid & 15;
    int j0   = rank * 64;

    // zero h staging (both parities)
    for (int i = tid; i < 2 * 2 * 264; i += 256)
        (&hA[0][0][0])[i] = __float2bfloat16(0.f);

    // ---- B-fragment preload: W[n][k] resident in registers ----------------
    unsigned Bf[4][16][2];
    {
        const float* wd = whh_l + (size_t)dir * G4 * HID;
        #pragma unroll
        for (int nt = 0; nt < 4; nt++) {
            int n = w * 32 + nt * 8 + gq;            // CTA-local gate index
            int g = n >> 6, jl = n & 63;
            const float* wp = wd + (size_t)(g * 256 + j0 + jl) * HID;
            #pragma unroll
            for (int kt = 0; kt < 16; kt++) {
                int k0 = kt * 16 + t2;
                float2 wa = *reinterpret_cast<const float2*>(wp + k0);
                float2 wb = *reinterpret_cast<const float2*>(wp + k0 + 8);
                __nv_bfloat162 qa = __float22bfloat162_rn(wa);
                __nv_bfloat162 qb = __float22bfloat162_rn(wb);
                Bf[nt][kt][0] = *reinterpret_cast<unsigned*>(&qa);
                Bf[nt][kt][1] = *reinterpret_cast<unsigned*>(&qb);
            }
        }
    }
    __syncthreads();
    asm volatile("barrier.cluster.arrive.aligned;" ::: "memory");
    asm volatile("barrier.cluster.wait.aligned;" ::: "memory");

    int bg0 = bp * 2;
    const float* xd = xw + (size_t)dir * MBT * G4;
    int xcol = (w >> 1) * 256 + j0 + (w & 1) * 32;   // global z-col base
    int brow = gq & 1;                               // A-row (= batch) for lanes 0-7

    // owner mapping: tid<128 -> batch ob, j-local ojl
    int ob = tid >> 6, ojl = tid & 63;
    int ojg = j0 + ojl;
    size_t yoff = ((size_t)(bg0 + ob) * SEQT) * DMOD + dir * HID + ojg;
    float cst = 0.f;

    unsigned hAbase;
    asm("{ .reg .u64 t; cvta.to.shared.u64 t, %1; cvt.u32.u64 %0, t; }"
        : "=r"(hAbase) : "l"(&hA[0][0][0]));

    // first step's x (accumulator init values, lanes 0-7)
    float2 xi[4];
    {
        int t0 = dir ? SEQT - 1 : 0;
        #pragma unroll
        for (int nt = 0; nt < 4; nt++) {
            xi[nt] = make_float2(0.f, 0.f);
            if (l < 8)
                xi[nt] = *reinterpret_cast<const float2*>(
                    xd + ((size_t)(bg0 + brow) * SEQT + t0) * G4 + xcol + nt * 8 + t2);
        }
    }

    unsigned zc = 0u;
    int par = 0;
    for (int s = 0; s < SEQT; s++) {
        int t = dir ? (SEQT - 1 - s) : s;

        // prefetch next step's x
        int sn = (s + 1 < SEQT) ? s + 1 : s;
        int tn = dir ? (SEQT - 1 - sn) : sn;
        float2 xn[4];
        #pragma unroll
        for (int nt = 0; nt < 4; nt++) {
            xn[nt] = make_float2(0.f, 0.f);
            if (l < 8)
                xn[nt] = *reinterpret_cast<const float2*>(
                    xd + ((size_t)(bg0 + brow) * SEQT + tn) * G4 + xcol + nt * 8 + t2);
        }

        // accumulators = x (bias folded); rows 8,9 unused -> 0
        float acc[4][4];
        #pragma unroll
        for (int nt = 0; nt < 4; nt++) {
            acc[nt][0] = xi[nt].x; acc[nt][1] = xi[nt].y;
            acc[nt][2] = 0.f;      acc[nt][3] = 0.f;
        }

        // mma over k = 256 (16 tiles)
        const __nv_bfloat16* hrow = &hA[par][brow][0];
        #pragma unroll
        for (int kt = 0; kt < 16; kt++) {
            unsigned a0 = 0u, a2 = 0u;
            if (l < 8) {
                a0 = *reinterpret_cast<const unsigned*>(hrow + kt * 16 + t2);
                a2 = *reinterpret_cast<const unsigned*>(hrow + kt * 16 + t2 + 8);
            }
            #pragma unroll
            for (int nt = 0; nt < 4; nt++)
                asm volatile(
                    "mma.sync.aligned.m16n8k16.row.col.f32.bf16.bf16.f32 "
                    "{%0,%1,%2,%3},{%4,%5,%6,%7},{%8,%9},{%0,%1,%2,%3};"
                    : "+f"(acc[nt][0]), "+f"(acc[nt][1]),
                      "+f"(acc[nt][2]), "+f"(acc[nt][3])
                    : "r"(a0), "r"(zc), "r"(a2), "r"(zc),
                      "r"(Bf[nt][kt][0]), "r"(Bf[nt][kt][1]));
        }

        // z -> smem (lanes 0-7 hold rows 0,1)
        if (l < 8) {
            #pragma unroll
            for (int nt = 0; nt < 4; nt++)
                *reinterpret_cast<float2*>(&zs[brow][w * 32 + nt * 8 + t2]) =
                    make_float2(acc[nt][0], acc[nt][1]);
        }
        __syncthreads();

        // owners (tid<128): one activation chain each + DSMEM broadcast
        __nv_bfloat16 hbq = __float2bfloat16(0.f);
        if (tid < 128) {
            float z0 = zs[ob][0 * 64 + ojl];
            float z1 = zs[ob][1 * 64 + ojl];
            float z2 = zs[ob][2 * 64 + ojl];
            float z3 = zs[ob][3 * 64 + ojl];
            cst = sigm_a(z1) * cst + sigm_a(z0) * tanh_a(z2);
            float h = sigm_a(z3) * tanh_a(cst);
            hbq = __float2bfloat16(h);

            unsigned uv = (unsigned)__bfloat16_as_ushort(hbq);
            unsigned nv = __shfl_down_sync(0xffffffffu, uv, 1);
            if (!(ojl & 1)) {
                unsigned pk = uv | (nv << 16);
                unsigned dst = hAbase +
                    (unsigned)((((par ^ 1) * 2 + ob) * 264 + ojg) * 2);
                #pragma unroll
                for (int r = 0; r < 4; r++) {
                    asm volatile(
                        "{ .reg .b32 ra; mapa.shared::cluster.u32 ra, %0, %1; "
                        "st.shared::cluster.b32 [ra], %2; }"
                        :: "r"(dst), "r"(r), "r"(pk) : "memory");
                }
            }
        }
        // arrive first; y store retires inside the barrier window
        asm volatile("barrier.cluster.arrive.aligned;" ::: "memory");
        if (tid < 128)
            yb[yoff + (size_t)t * DMOD] = hbq;
        asm volatile("barrier.cluster.wait.aligned;" ::: "memory");

        par ^= 1;
        #pragma unroll
        for (int nt = 0; nt < 4; nt++) xi[nt] = xn[nt];
    }
}

// ---------------------------------------------------------------------------
// K4: zero cont + mask
// ---------------------------------------------------------------------------
__global__ void zero_kernel() {
    int idx = blockIdx.x * blockDim.x + threadIdx.x;
    const int NC4 = (MENT * DMOD) / 4;
    if (idx < NC4) reinterpret_cast<float4*>(g_cont)[idx] = make_float4(0, 0, 0, 0);
    if (idx < MENT / 4) reinterpret_cast<float4*>(g_mask)[idx] = make_float4(0, 0, 0, 0);
}

// ---------------------------------------------------------------------------
// K5: ragged span mean-pool + scatter-add (atomic); reads bf16 activations
// ---------------------------------------------------------------------------
__global__ void span_pool_kernel(const __nv_bfloat16* __restrict__ x) {
    int be = blockIdx.x;
    int b = be >> 6;
    const int* ei = g_ent + be * 3;
    int id = ei[0], st = ei[1], en = ei[2];
    if (id < 0 || id >= ENT) return;
    int lo = st, hi = en;
    float sgn = 1.f;
    if (en < st) { lo = en; hi = st; sgn = -1.f; }
    lo = max(lo, 0); hi = min(hi, SEQT);
    float len = (float)max(en - st, 1);

    int d = threadIdx.x;                 // 128 lanes, 4 bf16 each
    float4 acc = make_float4(0, 0, 0, 0);
    const uint2* xp =
        reinterpret_cast<const uint2*>(x + (size_t)b * SEQT * DMOD) + d;
    for (int t = lo; t < hi; t++) {
        uint2 u = xp[(size_t)t * (DMOD / 4)];
        float2 a = __bfloat1622float2(*reinterpret_cast<__nv_bfloat162*>(&u.x));
        float2 bb = __bfloat1622float2(*reinterpret_cast<__nv_bfloat162*>(&u.y));
        acc.x += a.x; acc.y += a.y; acc.z += bb.x; acc.w += bb.y;
    }
    float invl = sgn / len;
    float* cp = g_cont + ((size_t)(b * ENT + id)) * DMOD + d * 4;
    atomicAdd(cp + 0, acc.x * invl);
    atomicAdd(cp + 1, acc.y * invl);
    atomicAdd(cp + 2, acc.z * invl);
    atomicAdd(cp + 3, acc.w * invl);
    if (d == 0) atomicAdd(&g_mask[b * ENT + id], 1.f);
}

// ---------------------------------------------------------------------------
// K6: LayerNorm over D=512 -> fp32 cw
// ---------------------------------------------------------------------------
__global__ __launch_bounds__(256)
void ln_kernel(const float* __restrict__ gw, const float* __restrict__ gb) {
    int row = blockIdx.x;
    int tid = threadIdx.x;
    const float* xr = g_cont + (size_t)row * DMOD;
    float v0 = xr[tid], v1 = xr[tid + 256];

    __shared__ float red[8];
    __shared__ float bc;
    int lane = tid & 31, warp = tid >> 5;

    float s = v0 + v1;
    #pragma unroll
    for (int o = 16; o; o >>= 1) s += __shfl_xor_sync(0xffffffffu, s, o);
    if (lane == 0) red[warp] = s;
    __syncthreads();
    if (tid == 0) {
        float t = 0;
        #pragma unroll
        for (int w = 0; w < 8; w++) t += red[w];
        bc = t * (1.f / DMOD);
    }
    __syncthreads();
    float mu = bc;
    __syncthreads();

    float d0 = v0 - mu, d1 = v1 - mu;
    float q = d0 * d0 + d1 * d1;
    #pragma unroll
    for (int o = 16; o; o >>= 1) q += __shfl_xor_sync(0xffffffffu, q, o);
    if (lane == 0) red[warp] = q;
    __syncthreads();
    if (tid == 0) {
        float t = 0;
        #pragma unroll
        for (int w = 0; w < 8; w++) t += red[w];
        bc = t * (1.f / DMOD);
    }
    __syncthreads();
    float inv = rsqrtf(bc + 1e-5f);

    float* o = g_cw + (size_t)row * DMOD;
    o[tid]       = d0 * inv * gw[tid]       + gb[tid];
    o[tid + 256] = d1 * inv * gw[tid + 256] + gb[tid + 256];
}

// ---------------------------------------------------------------------------
// K7: mask + log_softmax over R=64 (one warp per row, in-place on d_out)
// ---------------------------------------------------------------------------
__global__ __launch_bounds__(256)
void lsm_kernel(float* __restrict__ out) {
    int warp = threadIdx.x >> 5, lane = threadIdx.x & 31;
    int row = blockIdx.x * 8 + warp;
    int b = row >> 12, i = (row >> 6) & 63, j = row & 63;
    float m = fminf(g_mask[b * ENT + i], 1.f) * fminf(g_mask[b * ENT + j], 1.f);
    float* p = out + (size_t)row * REL;
    float v0 = p[lane] * m, v1 = p[lane + 32] * m;
    float mx = fmaxf(v0, v1);
    #pragma unroll
    for (int o = 16; o; o >>= 1) mx = fmaxf(mx, __shfl_xor_sync(0xffffffffu, mx, o));
    float s = expf(v0 - mx) + expf(v1 - mx);
    #pragma unroll
    for (int o = 16; o; o >>= 1) s += __shfl_xor_sync(0xffffffffu, s, o);
    float lse = mx + logf(s);
    p[lane] = v0 - lse;
    p[lane + 32] = v1 - lse;
}

// ---------------------------------------------------------------------------
// Host launch
// ---------------------------------------------------------------------------
extern "C" void kernel_launch(void* const* d_in, const int* in_sizes, int n_in,
                              void* d_out, int out_size) {
    int off = (in_sizes[2] == 1) ? 0 : -1;
    const unsigned* sents_raw = (const unsigned*)d_in[0];
    const unsigned* ent_raw   = (const unsigned*)d_in[1];
    const float* emb    = (const float*)d_in[3 + off];
    const float* Wih    = (const float*)d_in[4 + off];
    const float* Whh    = (const float*)d_in[5 + off];
    const float* bih    = (const float*)d_in[6 + off];
    const float* bhh    = (const float*)d_in[7 + off];
    const float* ln_g   = (const float*)d_in[8 + off];
    const float* ln_b   = (const float*)d_in[9 + off];
    const float* rel1_w = (const float*)d_in[10 + off];
    const float* rel1_b = (const float*)d_in[11 + off];
    const float* rel2_w = (const float*)d_in[12 + off];
    const float* rel2_b = (const float*)d_in[13 + off];
    const float* proj_w = (const float*)d_in[14 + off];
    const float* proj_b = (const float*)d_in[15 + off];
    const float* dec_w  = (const float*)d_in[16 + off];
    const float* dec_b  = (const float*)d_in[17 + off];
    float* out = (float*)d_out;

    float *p_xw, *p_bias, *p_cw, *p_r1, *p_r2;
    __nv_bfloat16 *p_xb, *p_cwb, *p_Tb, *p_wihb, *p_r1b, *p_r2b, *p_pjb, *p_dcb;
    cudaGetSymbolAddress((void**)&p_xw, g_xw);
    cudaGetSymbolAddress((void**)&p_bias, g_bias);
    cudaGetSymbolAddress((void**)&p_cw, g_cw);
    cudaGetSymbolAddress((void**)&p_r1, g_rel1);
    cudaGetSymbolAddress((void**)&p_r2, g_rel2);
    cudaGetSymbolAddress((void**)&p_xb, g_xb);
    cudaGetSymbolAddress((void**)&p_cwb, g_cwb);
    cudaGetSymbolAddress((void**)&p_Tb, g_Tb);
    cudaGetSymbolAddress((void**)&p_wihb, g_wihb);
    cudaGetSymbolAddress((void**)&p_r1b, g_r1b);
    cudaGetSymbolAddress((void**)&p_r2b, g_r2b);
    cudaGetSymbolAddress((void**)&p_pjb, g_pjb);
    cudaGetSymbolAddress((void**)&p_dcb, g_dcb);

    prep_idx_kernel<<<1, 256>>>(sents_raw, ent_raw);
    prep_bias_kernel<<<16, 256>>>(bih, bhh);
    f2b_kernel<<<2048, 256>>>(Wih, p_wihb, NLAY * 2 * G4 * DMOD / 4);
    f2b_kernel<<<256, 256>>>(rel1_w, p_r1b, DMOD * DMOD / 4);
    f2b_kernel<<<256, 256>>>(rel2_w, p_r2b, DMOD * DMOD / 4);
    f2b_kernel<<<256, 256>>>(proj_w, p_pjb, DMOD * DMOD / 4);
    f2b_kernel<<<32, 256>>>(dec_w, p_dcb, REL * DMOD / 4);
    embed_kernel<<<MBT, 128>>>(emb);

    for (int l = 0; l < NLAY; l++) {
        for (int dir = 0; dir < 2; dir++) {
            hgemm_nt<false, false, false><<<dim3(G4 / 64, MBT / 128), 256>>>(
                p_xb, p_wihb + (size_t)(l * 2 + dir) * G4 * DMOD,
                p_bias + (l * 2 + dir) * G4,
                p_xw + (size_t)dir * MBT * G4, nullptr,
                MBT, G4, DMOD, nullptr, nullptr);
        }
        // writes bf16 y into g_xb (next layer's input / final pooling source)
        lstm_mma_kernel<<<128, 256>>>(
            p_xw, Whh + (size_t)l * 2 * G4 * HID, p_xb);
    }

    zero_kernel<<<1024, 256>>>();
    span_pool_kernel<<<MENT, 128>>>(p_xb);
    ln_kernel<<<MENT, 256>>>(ln_g, ln_b);
    f2b_kernel<<<(MENT * DMOD / 4 + 255) / 256, 256>>>(p_cw, p_cwb, MENT * DMOD / 4);

    hgemm_nt<false, false, false><<<dim3(DMOD / 64, MENT / 128), 256>>>(
        p_cwb, p_r1b, rel1_b, p_r1, nullptr, MENT, DMOD, DMOD, nullptr, nullptr);
    hgemm_nt<false, false, false><<<dim3(DMOD / 64, MENT / 128), 256>>>(
        p_cwb, p_r2b, rel2_b, p_r2, nullptr, MENT, DMOD, DMOD, nullptr, nullptr);

    // pairwise: Tb = relu( relu(r1_j + r2_i) @ proj_w.T + proj_b )  (bf16 out)
    hgemm_nt<true, true, true><<<dim3(DMOD / 64, MPAIR / 128), 256>>>(
        nullptr, p_pjb, proj_b, nullptr, p_Tb, MPAIR, DMOD, DMOD, p_r1, p_r2);

    // logits = Tb @ dec_w.T + dec_b  -> d_out (fp32)
    hgemm_nt<false, false, false><<<dim3(REL / 64, MPAIR / 128), 256>>>(
        p_Tb, p_dcb, dec_b, out, nullptr, MPAIR, REL, DMOD, nullptr, nullptr);

    lsm_kernel<<<MPAIR / 8, 256>>>(out);
}

// round 14
// speedup vs baseline: 1.3589x; 1.0207x over previous
#include <cuda_runtime.h>
#include <cuda_bf16.h>
#include <cstddef>

// ---------------------------------------------------------------------------
// Problem constants
// ---------------------------------------------------------------------------
#define BATCH 32
#define SEQT  512
#define DMOD  512
#define HID   256
#define G4    1024          // 4*HID
#define ENT   64
#define REL   64
#define NLAY  2
#define MBT   (BATCH*SEQT)          // 16384 token rows
#define MPAIR (BATCH*ENT*ENT)       // 131072 pair rows
#define MENT  (BATCH*ENT)           // 2048 entity rows

// ---------------------------------------------------------------------------
// Device scratch (static allocation only — no cudaMalloc allowed)
// ---------------------------------------------------------------------------
__device__ __nv_bfloat16  g_xb[(size_t)MBT * DMOD];        // bf16 activations
__device__ float          g_xw[(size_t)2 * MBT * G4];      // per-dir input proj (fp32)
__device__ float          g_bias[NLAY * 2 * G4];           // bih+bhh
__device__ int            g_sents[MBT];
__device__ int            g_ent[MENT * 3];
__device__ float          g_cont[(size_t)MENT * DMOD];
__device__ float          g_mask[MENT];
__device__ float          g_cw[(size_t)MENT * DMOD];
__device__ __nv_bfloat16  g_cwb[(size_t)MENT * DMOD];
__device__ float          g_rel1[(size_t)MENT * DMOD];
__device__ float          g_rel2[(size_t)MENT * DMOD];
__device__ __nv_bfloat16  g_Tb[(size_t)MPAIR * DMOD];      // pair hidden, bf16
// bf16 weight copies
__device__ __nv_bfloat16  g_wihb[(size_t)NLAY * 2 * G4 * DMOD];
__device__ __nv_bfloat16  g_r1b[DMOD * DMOD];
__device__ __nv_bfloat16  g_r2b[DMOD * DMOD];
__device__ __nv_bfloat16  g_pjb[DMOD * DMOD];
__device__ __nv_bfloat16  g_dcb[REL * DMOD];

__device__ __forceinline__ float tanh_a(float x) {
    float r;
    asm("tanh.approx.f32 %0, %1;" : "=f"(r) : "f"(x));
    return r;
}
__device__ __forceinline__ float sigm_a(float x) {
    return fmaf(tanh_a(0.5f * x), 0.5f, 0.5f);
}

// ---------------------------------------------------------------------------
// K0: canonicalize sents / ent_inds (int64-or-int32 auto-detect) -> int32
// ---------------------------------------------------------------------------
__global__ void prep_idx_kernel(const unsigned* __restrict__ sents_raw,
                                const unsigned* __restrict__ ent_raw) {
    __shared__ int s64f, e64f;
    int tid = threadIdx.x;
    if (tid == 0) {
        bool s64 = true;
        for (int i = 0; i < 64; i++)
            if (sents_raw[2 * i + 1] != 0u) { s64 = false; break; }
        bool e64 = true;
        for (int i = 0; i < 64; i++) {
            unsigned lo = ent_raw[2 * i], hi = ent_raw[2 * i + 1];
            unsigned expct = ((int)lo < 0) ? 0xFFFFFFFFu : 0u;
            if (hi != expct) { e64 = false; break; }
        }
        s64f = s64; e64f = e64;
    }
    __syncthreads();
    int s64 = s64f, e64 = e64f;
    for (int i = tid; i < MBT; i += blockDim.x)
        g_sents[i] = s64 ? (int)sents_raw[2 * i] : (int)sents_raw[i];
    for (int i = tid; i < MENT * 3; i += blockDim.x)
        g_ent[i] = e64 ? (int)ent_raw[2 * i] : (int)ent_raw[i];
}

__global__ void prep_bias_kernel(const float* __restrict__ bih,
                                 const float* __restrict__ bhh) {
    int i = blockIdx.x * blockDim.x + threadIdx.x;
    if (i < NLAY * 2 * G4) g_bias[i] = bih[i] + bhh[i];
}

// ---------------------------------------------------------------------------
// f32 -> bf16 vectorized convert (n4 float4-groups)
// ---------------------------------------------------------------------------
__global__ void f2b_kernel(const float* __restrict__ src,
                           __nv_bfloat16* __restrict__ dst, int n4) {
    int i = blockIdx.x * blockDim.x + threadIdx.x;
    if (i >= n4) return;
    float4 v = reinterpret_cast<const float4*>(src)[i];
    __nv_bfloat162 lo = __float22bfloat162_rn(make_float2(v.x, v.y));
    __nv_bfloat162 hi = __float22bfloat162_rn(make_float2(v.z, v.w));
    uint2 u;
    u.x = *reinterpret_cast<unsigned*>(&lo);
    u.y = *reinterpret_cast<unsigned*>(&hi);
    reinterpret_cast<uint2*>(dst)[i] = u;
}

// ---------------------------------------------------------------------------
// K2: embedding gather -> bf16 activations
// ---------------------------------------------------------------------------
__global__ void embed_kernel(const float* __restrict__ emb) {
    int row = blockIdx.x;
    int d = threadIdx.x;                               // 128 float4 lanes
    int tok = g_sents[row];
    float4 v = reinterpret_cast<const float4*>(emb + (size_t)tok * DMOD)[d];
    __nv_bfloat162 lo = __float22bfloat162_rn(make_float2(v.x, v.y));
    __nv_bfloat162 hi = __float22bfloat162_rn(make_float2(v.z, v.w));
    uint2 u;
    u.x = *reinterpret_cast<unsigned*>(&lo);
    u.y = *reinterpret_cast<unsigned*>(&hi);
    reinterpret_cast<uint2*>(g_xb + (size_t)row * DMOD)[d] = u;
}

// ---------------------------------------------------------------------------
// bf16 tensor-core GEMM: C[M,N] = A[M,K] @ W[N,K]^T + bias, fp32 accum.
// BM=128 BN=64 BK=32, 256 thr (8 warps, 4x2), warp tile 32x32 via mma.m16n8k16.
// Double-buffered smem (1 syncthreads per k-tile) + ldmatrix.x4 fragment loads.
// GEN: A generated on the fly as relu(r1[b,j]+r2[b,i]); OUTB: bf16 output.
// ---------------------------------------------------------------------------
template <bool GEN, bool OUTB, bool RELU>
__global__ __launch_bounds__(256)
void hgemm_nt(const __nv_bfloat16* __restrict__ A,
              const __nv_bfloat16* __restrict__ Bw,
              const float* __restrict__ bias,
              float* __restrict__ Cf, __nv_bfloat16* __restrict__ Cb,
              int M, int N, int K,
              const float* __restrict__ r1, const float* __restrict__ r2) {
    const int BM = 128, BN = 64, BK = 32, LDA = BK + 8;   // 80-byte rows (16B mult)
    __shared__ __align__(16) __nv_bfloat16 As[2][BM * LDA];
    __shared__ __align__(16) __nv_bfloat16 Bs[2][BN * LDA];
    int tid = threadIdx.x;
    int row0 = blockIdx.y * BM, col0 = blockIdx.x * BN;

    int ar[2], ac[2];
    #pragma unroll
    for (int q = 0; q < 2; q++) {
        int idx = tid + q * 256;
        ar[q] = idx >> 2;
        ac[q] = (idx & 3) * 8;
    }
    int br = tid >> 2, bc = (tid & 3) * 8;

    float acc[2][4][4];
    #pragma unroll
    for (int i = 0; i < 2; i++)
        #pragma unroll
        for (int j = 0; j < 4; j++)
            #pragma unroll
            for (int c = 0; c < 4; c++) acc[i][j][c] = 0.f;

    uint4 ua[2], ub;
    auto fetch = [&](int kt) {
        #pragma unroll
        for (int q = 0; q < 2; q++) {
            int m = row0 + ar[q];
            if (!GEN) {
                ua[q] = *reinterpret_cast<const uint4*>(A + (size_t)m * K + kt + ac[q]);
            } else {
                int bb = m >> 12, ii = (m >> 6) & 63, jj = m & 63;
                const float4* p1 = reinterpret_cast<const float4*>(
                    r1 + ((size_t)(bb * ENT + jj)) * DMOD + kt + ac[q]);
                const float4* p2 = reinterpret_cast<const float4*>(
                    r2 + ((size_t)(bb * ENT + ii)) * DMOD + kt + ac[q]);
                float4 x0 = p1[0], x1 = p1[1], y0 = p2[0], y1 = p2[1];
                float f0 = fmaxf(x0.x + y0.x, 0.f), f1 = fmaxf(x0.y + y0.y, 0.f);
                float f2 = fmaxf(x0.z + y0.z, 0.f), f3 = fmaxf(x0.w + y0.w, 0.f);
                float f4 = fmaxf(x1.x + y1.x, 0.f), f5 = fmaxf(x1.y + y1.y, 0.f);
                float f6 = fmaxf(x1.z + y1.z, 0.f), f7 = fmaxf(x1.w + y1.w, 0.f);
                __nv_bfloat162 h0 = __float22bfloat162_rn(make_float2(f0, f1));
                __nv_bfloat162 h1 = __float22bfloat162_rn(make_float2(f2, f3));
                __nv_bfloat162 h2 = __float22bfloat162_rn(make_float2(f4, f5));
                __nv_bfloat162 h3 = __float22bfloat162_rn(make_float2(f6, f7));
                ua[q].x = *reinterpret_cast<unsigned*>(&h0);
                ua[q].y = *reinterpret_cast<unsigned*>(&h1);
                ua[q].z = *reinterpret_cast<unsigned*>(&h2);
                ua[q].w = *reinterpret_cast<unsigned*>(&h3);
            }
        }
        ub = *reinterpret_cast<const uint4*>(Bw + (size_t)(col0 + br) * K + kt + bc);
    };
    auto stage = [&](int buf) {
        *reinterpret_cast<uint4*>(&As[buf][ar[0] * LDA + ac[0]]) = ua[0];
        *reinterpret_cast<uint4*>(&As[buf][ar[1] * LDA + ac[1]]) = ua[1];
        *reinterpret_cast<uint4*>(&Bs[buf][br * LDA + bc]) = ub;
    };

    int w = tid >> 5, wm = w & 3, wn = w >> 2, l = tid & 31;
    int lr = l >> 2, lc = (l & 3) * 2;

    // ldmatrix per-lane row/col mapping (see theory: matches mma fragment layout)
    int a_row = wm * 32 + ((l >> 3) & 1) * 8 + (l & 7);   // + i*16
    int a_col = (l >> 4) * 8;                              // + s*16
    int b_row = wn * 32 + (l >> 4) * 8 + (l & 7);          // + jp*16
    int b_col = ((l >> 3) & 1) * 8;                        // + s*16
    unsigned sAu = (unsigned)__cvta_generic_to_shared(&As[0][0]);
    unsigned sBu = (unsigned)__cvta_generic_to_shared(&Bs[0][0]);
    const unsigned bufAB = (unsigned)(BM * LDA * 2);
    const unsigned bufBB = (unsigned)(BN * LDA * 2);
    unsigned aAddr = sAu + (unsigned)((a_row * LDA + a_col) * 2);
    unsigned bAddr = sBu + (unsigned)((b_row * LDA + b_col) * 2);

    fetch(0);
    stage(0);
    __syncthreads();

    int nk = K / BK;
    for (int kt = 0; kt < nk; kt++) {
        int cur = kt & 1;
        if (kt + 1 < nk) fetch((kt + 1) * BK);

        unsigned aBuf = aAddr + cur * bufAB;
        unsigned bBuf = bAddr + cur * bufBB;
        #pragma unroll
        for (int s = 0; s < 2; s++) {
            unsigned a[2][4], b[4][2];
            #pragma unroll
            for (int i = 0; i < 2; i++) {
                unsigned ad = aBuf + (unsigned)((i * 16 * LDA + s * 16) * 2);
                asm volatile(
                    "ldmatrix.sync.aligned.m8n8.x4.shared.b16 {%0,%1,%2,%3}, [%4];"
                    : "=r"(a[i][0]), "=r"(a[i][1]), "=r"(a[i][2]), "=r"(a[i][3])
                    : "r"(ad));
            }
            #pragma unroll
            for (int jp = 0; jp < 2; jp++) {
                unsigned bd = bBuf + (unsigned)((jp * 16 * LDA + s * 16) * 2);
                asm volatile(
                    "ldmatrix.sync.aligned.m8n8.x4.shared.b16 {%0,%1,%2,%3}, [%4];"
                    : "=r"(b[2 * jp][0]), "=r"(b[2 * jp][1]),
                      "=r"(b[2 * jp + 1][0]), "=r"(b[2 * jp + 1][1])
                    : "r"(bd));
            }
            #pragma unroll
            for (int i = 0; i < 2; i++)
                #pragma unroll
                for (int j = 0; j < 4; j++)
                    asm volatile(
                        "mma.sync.aligned.m16n8k16.row.col.f32.bf16.bf16.f32 "
                        "{%0,%1,%2,%3},{%4,%5,%6,%7},{%8,%9},{%0,%1,%2,%3};"
                        : "+f"(acc[i][j][0]), "+f"(acc[i][j][1]),
                          "+f"(acc[i][j][2]), "+f"(acc[i][j][3])
                        : "r"(a[i][0]), "r"(a[i][1]), "r"(a[i][2]), "r"(a[i][3]),
                          "r"(b[j][0]), "r"(b[j][1]));
        }

        if (kt + 1 < nk) {
            stage(cur ^ 1);
            __syncthreads();
        }
    }

    // epilogue
    #pragma unroll
    for (int i = 0; i < 2; i++) {
        int m = row0 + wm * 32 + i * 16 + lr;
        #pragma unroll
        for (int j = 0; j < 4; j++) {
            int col = col0 + wn * 32 + j * 8 + lc;
            float b0 = bias[col], b1 = bias[col + 1];
            float v0 = acc[i][j][0] + b0, v1 = acc[i][j][1] + b1;
            float v2 = acc[i][j][2] + b0, v3 = acc[i][j][3] + b1;
            if (RELU) {
                v0 = fmaxf(v0, 0.f); v1 = fmaxf(v1, 0.f);
                v2 = fmaxf(v2, 0.f); v3 = fmaxf(v3, 0.f);
            }
            if (OUTB) {
                __nv_bfloat162 p0 = __float22bfloat162_rn(make_float2(v0, v1));
                __nv_bfloat162 p1 = __float22bfloat162_rn(make_float2(v2, v3));
                *reinterpret_cast<__nv_bfloat162*>(Cb + (size_t)m * N + col) = p0;
                *reinterpret_cast<__nv_bfloat162*>(Cb + (size_t)(m + 8) * N + col) = p1;
            } else {
                *reinterpret_cast<float2*>(Cf + (size_t)m * N + col) = make_float2(v0, v1);
                *reinterpret_cast<float2*>(Cf + (size_t)(m + 8) * N + col) = make_float2(v2, v3);
            }
        }
    }
}

// ---------------------------------------------------------------------------
// K3: LSTM recurrence on tensor cores, 4-CTA cluster, 2 batches per cluster.
// R13 winner (unchanged): fp32 x-proj, per-step hardware cluster.sync, 128
// B-fragment registers/thread, 128 owner threads (one activation chain each),
// hoisted cluster arrive, bf16-only y.
// ---------------------------------------------------------------------------
__global__ void __cluster_dims__(4, 1, 1) __launch_bounds__(256, 1)
lstm_mma_kernel(const float* __restrict__ xw,
                const float* __restrict__ whh_l,   // fp32 [2][G4][HID]
                __nv_bfloat16* __restrict__ yb) {
    __shared__ __align__(16) __nv_bfloat16 hA[2][2][264];  // [par][batch][k]
    __shared__ __align__(16) float zs[2][260];             // [batch][n]

    int tid = threadIdx.x;
    int w = tid >> 5, l = tid & 31;
    int gq = l >> 2, t2 = (l & 3) * 2;
    int rank = blockIdx.x & 3;
    int cid  = blockIdx.x >> 2;
    int dir  = cid >> 4;
    int bp   = cid & 15;
    int j0   = rank * 64;

    // zero h staging (both parities)
    for (int i = tid; i < 2 * 2 * 264; i += 256)
        (&hA[0][0][0])[i] = __float2bfloat16(0.f);

    // ---- B-fragment preload: W[n][k] resident in registers ----------------
    unsigned Bf[4][16][2];
    {
        const float* wd = whh_l + (size_t)dir * G4 * HID;
        #pragma unroll
        for (int nt = 0; nt < 4; nt++) {
            int n = w * 32 + nt * 8 + gq;            // CTA-local gate index
            int g = n >> 6, jl = n & 63;
            const float* wp = wd + (size_t)(g * 256 + j0 + jl) * HID;
            #pragma unroll
            for (int kt = 0; kt < 16; kt++) {
                int k0 = kt * 16 + t2;
                float2 wa = *reinterpret_cast<const float2*>(wp + k0);
                float2 wb = *reinterpret_cast<const float2*>(wp + k0 + 8);
                __nv_bfloat162 qa = __float22bfloat162_rn(wa);
                __nv_bfloat162 qb = __float22bfloat162_rn(wb);
                Bf[nt][kt][0] = *reinterpret_cast<unsigned*>(&qa);
                Bf[nt][kt][1] = *reinterpret_cast<unsigned*>(&qb);
            }
        }
    }
    __syncthreads();
    asm volatile("barrier.cluster.arrive.aligned;" ::: "memory");
    asm volatile("barrier.cluster.wait.aligned;" ::: "memory");

    int bg0 = bp * 2;
    const float* xd = xw + (size_t)dir * MBT * G4;
    int xcol = (w >> 1) * 256 + j0 + (w & 1) * 32;   // global z-col base
    int brow = gq & 1;                               // A-row (= batch) for lanes 0-7

    // owner mapping: tid<128 -> batch ob, j-local ojl
    int ob = tid >> 6, ojl = tid & 63;
    int ojg = j0 + ojl;
    size_t yoff = ((size_t)(bg0 + ob) * SEQT) * DMOD + dir * HID + ojg;
    float cst = 0.f;

    unsigned hAbase;
    asm("{ .reg .u64 t; cvta.to.shared.u64 t, %1; cvt.u32.u64 %0, t; }"
        : "=r"(hAbase) : "l"(&hA[0][0][0]));

    // first step's x (accumulator init values, lanes 0-7)
    float2 xi[4];
    {
        int t0 = dir ? SEQT - 1 : 0;
        #pragma unroll
        for (int nt = 0; nt < 4; nt++) {
            xi[nt] = make_float2(0.f, 0.f);
            if (l < 8)
                xi[nt] = *reinterpret_cast<const float2*>(
                    xd + ((size_t)(bg0 + brow) * SEQT + t0) * G4 + xcol + nt * 8 + t2);
        }
    }

    unsigned zc = 0u;
    int par = 0;
    for (int s = 0; s < SEQT; s++) {
        int t = dir ? (SEQT - 1 - s) : s;

        // prefetch next step's x
        int sn = (s + 1 < SEQT) ? s + 1 : s;
        int tn = dir ? (SEQT - 1 - sn) : sn;
        float2 xn[4];
        #pragma unroll
        for (int nt = 0; nt < 4; nt++) {
            xn[nt] = make_float2(0.f, 0.f);
            if (l < 8)
                xn[nt] = *reinterpret_cast<const float2*>(
                    xd + ((size_t)(bg0 + brow) * SEQT + tn) * G4 + xcol + nt * 8 + t2);
        }

        // accumulators = x (bias folded); rows 8,9 unused -> 0
        float acc[4][4];
        #pragma unroll
        for (int nt = 0; nt < 4; nt++) {
            acc[nt][0] = xi[nt].x; acc[nt][1] = xi[nt].y;
            acc[nt][2] = 0.f;      acc[nt][3] = 0.f;
        }

        // mma over k = 256 (16 tiles)
        const __nv_bfloat16* hrow = &hA[par][brow][0];
        #pragma unroll
        for (int kt = 0; kt < 16; kt++) {
            unsigned a0 = 0u, a2 = 0u;
            if (l < 8) {
                a0 = *reinterpret_cast<const unsigned*>(hrow + kt * 16 + t2);
                a2 = *reinterpret_cast<const unsigned*>(hrow + kt * 16 + t2 + 8);
            }
            #pragma unroll
            for (int nt = 0; nt < 4; nt++)
                asm volatile(
                    "mma.sync.aligned.m16n8k16.row.col.f32.bf16.bf16.f32 "
                    "{%0,%1,%2,%3},{%4,%5,%6,%7},{%8,%9},{%0,%1,%2,%3};"
                    : "+f"(acc[nt][0]), "+f"(acc[nt][1]),
                      "+f"(acc[nt][2]), "+f"(acc[nt][3])
                    : "r"(a0), "r"(zc), "r"(a2), "r"(zc),
                      "r"(Bf[nt][kt][0]), "r"(Bf[nt][kt][1]));
        }

        // z -> smem (lanes 0-7 hold rows 0,1)
        if (l < 8) {
            #pragma unroll
            for (int nt = 0; nt < 4; nt++)
                *reinterpret_cast<float2*>(&zs[brow][w * 32 + nt * 8 + t2]) =
                    make_float2(acc[nt][0], acc[nt][1]);
        }
        __syncthreads();

        // owners (tid<128): one activation chain each + DSMEM broadcast
        __nv_bfloat16 hbq = __float2bfloat16(0.f);
        if (tid < 128) {
            float z0 = zs[ob][0 * 64 + ojl];
            float z1 = zs[ob][1 * 64 + ojl];
            float z2 = zs[ob][2 * 64 + ojl];
            float z3 = zs[ob][3 * 64 + ojl];
            cst = sigm_a(z1) * cst + sigm_a(z0) * tanh_a(z2);
            float h = sigm_a(z3) * tanh_a(cst);
            hbq = __float2bfloat16(h);

            unsigned uv = (unsigned)__bfloat16_as_ushort(hbq);
            unsigned nv = __shfl_down_sync(0xffffffffu, uv, 1);
            if (!(ojl & 1)) {
                unsigned pk = uv | (nv << 16);
                unsigned dst = hAbase +
                    (unsigned)((((par ^ 1) * 2 + ob) * 264 + ojg) * 2);
                #pragma unroll
                for (int r = 0; r < 4; r++) {
                    asm volatile(
                        "{ .reg .b32 ra; mapa.shared::cluster.u32 ra, %0, %1; "
                        "st.shared::cluster.b32 [ra], %2; }"
                        :: "r"(dst), "r"(r), "r"(pk) : "memory");
                }
            }
        }
        // arrive first; y store retires inside the barrier window
        asm volatile("barrier.cluster.arrive.aligned;" ::: "memory");
        if (tid < 128)
            yb[yoff + (size_t)t * DMOD] = hbq;
        asm volatile("barrier.cluster.wait.aligned;" ::: "memory");

        par ^= 1;
        #pragma unroll
        for (int nt = 0; nt < 4; nt++) xi[nt] = xn[nt];
    }
}

// ---------------------------------------------------------------------------
// K4: zero cont + mask
// ---------------------------------------------------------------------------
__global__ void zero_kernel() {
    int idx = blockIdx.x * blockDim.x + threadIdx.x;
    const int NC4 = (MENT * DMOD) / 4;
    if (idx < NC4) reinterpret_cast<float4*>(g_cont)[idx] = make_float4(0, 0, 0, 0);
    if (idx < MENT / 4) reinterpret_cast<float4*>(g_mask)[idx] = make_float4(0, 0, 0, 0);
}

// ---------------------------------------------------------------------------
// K5: ragged span mean-pool + scatter-add (atomic); reads bf16 activations
// ---------------------------------------------------------------------------
__global__ void span_pool_kernel(const __nv_bfloat16* __restrict__ x) {
    int be = blockIdx.x;
    int b = be >> 6;
    const int* ei = g_ent + be * 3;
    int id = ei[0], st = ei[1], en = ei[2];
    if (id < 0 || id >= ENT) return;
    int lo = st, hi = en;
    float sgn = 1.f;
    if (en < st) { lo = en; hi = st; sgn = -1.f; }
    lo = max(lo, 0); hi = min(hi, SEQT);
    float len = (float)max(en - st, 1);

    int d = threadIdx.x;                 // 128 lanes, 4 bf16 each
    float4 acc = make_float4(0, 0, 0, 0);
    const uint2* xp =
        reinterpret_cast<const uint2*>(x + (size_t)b * SEQT * DMOD) + d;
    for (int t = lo; t < hi; t++) {
        uint2 u = xp[(size_t)t * (DMOD / 4)];
        float2 a = __bfloat1622float2(*reinterpret_cast<__nv_bfloat162*>(&u.x));
        float2 bb = __bfloat1622float2(*reinterpret_cast<__nv_bfloat162*>(&u.y));
        acc.x += a.x; acc.y += a.y; acc.z += bb.x; acc.w += bb.y;
    }
    float invl = sgn / len;
    float* cp = g_cont + ((size_t)(b * ENT + id)) * DMOD + d * 4;
    atomicAdd(cp + 0, acc.x * invl);
    atomicAdd(cp + 1, acc.y * invl);
    atomicAdd(cp + 2, acc.z * invl);
    atomicAdd(cp + 3, acc.w * invl);
    if (d == 0) atomicAdd(&g_mask[b * ENT + id], 1.f);
}

// ---------------------------------------------------------------------------
// K6: LayerNorm over D=512 -> fp32 cw
// ---------------------------------------------------------------------------
__global__ __launch_bounds__(256)
void ln_kernel(const float* __restrict__ gw, const float* __restrict__ gb) {
    int row = blockIdx.x;
    int tid = threadIdx.x;
    const float* xr = g_cont + (size_t)row * DMOD;
    float v0 = xr[tid], v1 = xr[tid + 256];

    __shared__ float red[8];
    __shared__ float bc;
    int lane = tid & 31, warp = tid >> 5;

    float s = v0 + v1;
    #pragma unroll
    for (int o = 16; o; o >>= 1) s += __shfl_xor_sync(0xffffffffu, s, o);
    if (lane == 0) red[warp] = s;
    __syncthreads();
    if (tid == 0) {
        float t = 0;
        #pragma unroll
        for (int w = 0; w < 8; w++) t += red[w];
        bc = t * (1.f / DMOD);
    }
    __syncthreads();
    float mu = bc;
    __syncthreads();

    float d0 = v0 - mu, d1 = v1 - mu;
    float q = d0 * d0 + d1 * d1;
    #pragma unroll
    for (int o = 16; o; o >>= 1) q += __shfl_xor_sync(0xffffffffu, q, o);
    if (lane == 0) red[warp] = q;
    __syncthreads();
    if (tid == 0) {
        float t = 0;
        #pragma unroll
        for (int w = 0; w < 8; w++) t += red[w];
        bc = t * (1.f / DMOD);
    }
    __syncthreads();
    float inv = rsqrtf(bc + 1e-5f);

    float* o = g_cw + (size_t)row * DMOD;
    o[tid]       = d0 * inv * gw[tid]       + gb[tid];
    o[tid + 256] = d1 * inv * gw[tid + 256] + gb[tid + 256];
}

// ---------------------------------------------------------------------------
// K7: mask + log_softmax over R=64 (one warp per row, in-place on d_out)
// ---------------------------------------------------------------------------
__global__ __launch_bounds__(256)
void lsm_kernel(float* __restrict__ out) {
    int warp = threadIdx.x >> 5, lane = threadIdx.x & 31;
    int row = blockIdx.x * 8 + warp;
    int b = row >> 12, i = (row >> 6) & 63, j = row & 63;
    float m = fminf(g_mask[b * ENT + i], 1.f) * fminf(g_mask[b * ENT + j], 1.f);
    float* p = out + (size_t)row * REL;
    float v0 = p[lane] * m, v1 = p[lane + 32] * m;
    float mx = fmaxf(v0, v1);
    #pragma unroll
    for (int o = 16; o; o >>= 1) mx = fmaxf(mx, __shfl_xor_sync(0xffffffffu, mx, o));
    float s = expf(v0 - mx) + expf(v1 - mx);
    #pragma unroll
    for (int o = 16; o; o >>= 1) s += __shfl_xor_sync(0xffffffffu, s, o);
    float lse = mx + logf(s);
    p[lane] = v0 - lse;
    p[lane + 32] = v1 - lse;
}

// ---------------------------------------------------------------------------
// Host launch
// ---------------------------------------------------------------------------
extern "C" void kernel_launch(void* const* d_in, const int* in_sizes, int n_in,
                              void* d_out, int out_size) {
    int off = (in_sizes[2] == 1) ? 0 : -1;
    const unsigned* sents_raw = (const unsigned*)d_in[0];
    const unsigned* ent_raw   = (const unsigned*)d_in[1];
    const float* emb    = (const float*)d_in[3 + off];
    const float* Wih    = (const float*)d_in[4 + off];
    const float* Whh    = (const float*)d_in[5 + off];
    const float* bih    = (const float*)d_in[6 + off];
    const float* bhh    = (const float*)d_in[7 + off];
    const float* ln_g   = (const float*)d_in[8 + off];
    const float* ln_b   = (const float*)d_in[9 + off];
    const float* rel1_w = (const float*)d_in[10 + off];
    const float* rel1_b = (const float*)d_in[11 + off];
    const float* rel2_w = (const float*)d_in[12 + off];
    const float* rel2_b = (const float*)d_in[13 + off];
    const float* proj_w = (const float*)d_in[14 + off];
    const float* proj_b = (const float*)d_in[15 + off];
    const float* dec_w  = (const float*)d_in[16 + off];
    const float* dec_b  = (const float*)d_in[17 + off];
    float* out = (float*)d_out;

    float *p_xw, *p_bias, *p_cw, *p_r1, *p_r2;
    __nv_bfloat16 *p_xb, *p_cwb, *p_Tb, *p_wihb, *p_r1b, *p_r2b, *p_pjb, *p_dcb;
    cudaGetSymbolAddress((void**)&p_xw, g_xw);
    cudaGetSymbolAddress((void**)&p_bias, g_bias);
    cudaGetSymbolAddress((void**)&p_cw, g_cw);
    cudaGetSymbolAddress((void**)&p_r1, g_rel1);
    cudaGetSymbolAddress((void**)&p_r2, g_rel2);
    cudaGetSymbolAddress((void**)&p_xb, g_xb);
    cudaGetSymbolAddress((void**)&p_cwb, g_cwb);
    cudaGetSymbolAddress((void**)&p_Tb, g_Tb);
    cudaGetSymbolAddress((void**)&p_wihb, g_wihb);
    cudaGetSymbolAddress((void**)&p_r1b, g_r1b);
    cudaGetSymbolAddress((void**)&p_r2b, g_r2b);
    cudaGetSymbolAddress((void**)&p_pjb, g_pjb);
    cudaGetSymbolAddress((void**)&p_dcb, g_dcb);

    prep_idx_kernel<<<1, 256>>>(sents_raw, ent_raw);
    prep_bias_kernel<<<16, 256>>>(bih, bhh);
    f2b_kernel<<<2048, 256>>>(Wih, p_wihb, NLAY * 2 * G4 * DMOD / 4);
    f2b_kernel<<<256, 256>>>(rel1_w, p_r1b, DMOD * DMOD / 4);
    f2b_kernel<<<256, 256>>>(rel2_w, p_r2b, DMOD * DMOD / 4);
    f2b_kernel<<<256, 256>>>(proj_w, p_pjb, DMOD * DMOD / 4);
    f2b_kernel<<<32, 256>>>(dec_w, p_dcb, REL * DMOD / 4);
    embed_kernel<<<MBT, 128>>>(emb);

    for (int l = 0; l < NLAY; l++) {
        for (int dir = 0; dir < 2; dir++) {
            hgemm_nt<false, false, false><<<dim3(G4 / 64, MBT / 128), 256>>>(
                p_xb, p_wihb + (size_t)(l * 2 + dir) * G4 * DMOD,
                p_bias + (l * 2 + dir) * G4,
                p_xw + (size_t)dir * MBT * G4, nullptr,
                MBT, G4, DMOD, nullptr, nullptr);
        }
        // writes bf16 y into g_xb (next layer's input / final pooling source)
        lstm_mma_kernel<<<128, 256>>>(
            p_xw, Whh + (size_t)l * 2 * G4 * HID, p_xb);
    }

    zero_kernel<<<1024, 256>>>();
    span_pool_kernel<<<MENT, 128>>>(p_xb);
    ln_kernel<<<MENT, 256>>>(ln_g, ln_b);
    f2b_kernel<<<(MENT * DMOD / 4 + 255) / 256, 256>>>(p_cw, p_cwb, MENT * DMOD / 4);

    hgemm_nt<false, false, false><<<dim3(DMOD / 64, MENT / 128), 256>>>(
        p_cwb, p_r1b, rel1_b, p_r1, nullptr, MENT, DMOD, DMOD, nullptr, nullptr);
    hgemm_nt<false, false, false><<<dim3(DMOD / 64, MENT / 128), 256>>>(
        p_cwb, p_r2b, rel2_b, p_r2, nullptr, MENT, DMOD, DMOD, nullptr, nullptr);

    // pairwise: Tb = relu( relu(r1_j + r2_i) @ proj_w.T + proj_b )  (bf16 out)
    hgemm_nt<true, true, true><<<dim3(DMOD / 64, MPAIR / 128), 256>>>(
        nullptr, p_pjb, proj_b, nullptr, p_Tb, MPAIR, DMOD, DMOD, p_r1, p_r2);

    // logits = Tb @ dec_w.T + dec_b  -> d_out (fp32)
    hgemm_nt<false, false, false><<<dim3(REL / 64, MPAIR / 128), 256>>>(
        p_Tb, p_dcb, dec_b, out, nullptr, MPAIR, REL, DMOD, nullptr, nullptr);

    lsm_kernel<<<MPAIR / 8, 256>>>(out);
}